// round 1
// baseline (speedup 1.0000x reference)
#include <cuda_runtime.h>

// Problem constants (fixed shapes from the reference)
#define NMAX 50000
#define EMAX 800000
#define INC  256
#define NHEAD 8
#define CH   32
#define HC   256   // NHEAD*CH

// ---------------- scratch (static device globals; no allocs allowed) -------
__device__ float    g_xh[NMAX * HC];            // projected features (N,H,C)
__device__ float    g_asrc[NMAX * NHEAD];       // per-node src logits
__device__ float    g_adst[NMAX * NHEAD];       // per-node dst logits
__device__ unsigned g_mmax[NMAX * NHEAD];       // encoded segment max
__device__ float    g_denom[NMAX * NHEAD];      // softmax denominators
__device__ int      g_edges[2 * EMAX];          // converted int32 edge index
__device__ float    g_ex[(EMAX + NMAX) * NHEAD];// exp(e - m) per edge
__device__ int      g_is64;

// ------------- float <-> orderable unsigned encoding for atomicMax ---------
__device__ __forceinline__ unsigned fenc(float f) {
    unsigned u = __float_as_uint(f);
    return (u & 0x80000000u) ? ~u : (u | 0x80000000u);
}
__device__ __forceinline__ float fdec(unsigned v) {
    return (v & 0x80000000u) ? __uint_as_float(v & 0x7FFFFFFFu)
                             : __uint_as_float(~v);
}

// ---------------- K0: detect int64 vs int32 edge_index ---------------------
__global__ void k_detect(const int* __restrict__ p, int n_words) {
    __shared__ int s;
    if (threadIdx.x == 0) s = 0;
    __syncthreads();
    int acc = 0;
    for (int i = 1 + 2 * (int)threadIdx.x; i < n_words; i += 2 * blockDim.x)
        acc |= p[i];
    if (acc) atomicOr(&s, 1);
    __syncthreads();
    if (threadIdx.x == 0) g_is64 = (s == 0) ? 1 : 0;
}

// ---------------- K1: convert edge index to int32 --------------------------
__global__ void k_convert(const void* __restrict__ p, int twoE) {
    int i = blockIdx.x * blockDim.x + threadIdx.x;
    if (i >= twoE) return;
    if (g_is64) g_edges[i] = (int)((const long long*)p)[i];
    else        g_edges[i] = ((const int*)p)[i];
}

// ---------------- K2: xh = x @ W  (N,256)x(256,256) ------------------------
#define BM 64
#define BN 64
#define BK 16
__global__ __launch_bounds__(256) void k_gemm(const float* __restrict__ A,
                                              const float* __restrict__ B,
                                              int Nn) {
    __shared__ float As[BK][BM];
    __shared__ float Bs[BK][BN + 4];
    int tid = threadIdx.x;
    int block_row = blockIdx.x * BM;
    int block_col = blockIdx.y * BN;
    int tx = tid % 16, ty = tid / 16;

    float acc[4][4] = {};
    for (int k0 = 0; k0 < INC; k0 += BK) {
        // load A tile (BM x BK) as float4 per thread, store transposed
        {
            int r  = tid >> 2;          // 0..63
            int c4 = (tid & 3) << 2;    // 0,4,8,12
            float4 v = make_float4(0.f, 0.f, 0.f, 0.f);
            int gr = block_row + r;
            if (gr < Nn) v = *(const float4*)&A[(size_t)gr * INC + k0 + c4];
            As[c4 + 0][r] = v.x; As[c4 + 1][r] = v.y;
            As[c4 + 2][r] = v.z; As[c4 + 3][r] = v.w;
        }
        // load B tile (BK x BN)
        {
            int r  = tid >> 4;          // 0..15
            int c4 = (tid & 15) << 2;   // 0..60
            float4 v = *(const float4*)&B[(size_t)(k0 + r) * HC + block_col + c4];
            Bs[r][c4 + 0] = v.x; Bs[r][c4 + 1] = v.y;
            Bs[r][c4 + 2] = v.z; Bs[r][c4 + 3] = v.w;
        }
        __syncthreads();
#pragma unroll
        for (int k = 0; k < BK; k++) {
            float a[4], b[4];
#pragma unroll
            for (int i = 0; i < 4; i++) a[i] = As[k][ty * 4 + i];
#pragma unroll
            for (int j = 0; j < 4; j++) b[j] = Bs[k][tx * 4 + j];
#pragma unroll
            for (int i = 0; i < 4; i++)
#pragma unroll
                for (int j = 0; j < 4; j++) acc[i][j] += a[i] * b[j];
        }
        __syncthreads();
    }
#pragma unroll
    for (int i = 0; i < 4; i++) {
        int gr = block_row + ty * 4 + i;
        if (gr < Nn) {
            float4 v = make_float4(acc[i][0], acc[i][1], acc[i][2], acc[i][3]);
            *(float4*)&g_xh[(size_t)gr * HC + block_col + tx * 4] = v;
        }
    }
}

// ---------------- K3: per-node attention logits -----------------------------
__global__ void k_logits(const float* __restrict__ att_src,
                         const float* __restrict__ att_dst, int Nn) {
    int w    = (blockIdx.x * blockDim.x + threadIdx.x) >> 5;
    int lane = threadIdx.x & 31;
    if (w >= Nn * NHEAD) return;
    int n = w / NHEAD, h = w % NHEAD;
    float xv = g_xh[(size_t)n * HC + h * CH + lane];
    float s = xv * att_src[h * CH + lane];
    float d = xv * att_dst[h * CH + lane];
#pragma unroll
    for (int o = 16; o > 0; o >>= 1) {
        s += __shfl_down_sync(0xFFFFFFFFu, s, o);
        d += __shfl_down_sync(0xFFFFFFFFu, d, o);
    }
    if (lane == 0) { g_asrc[w] = s; g_adst[w] = d; }
}

// ---------------- K4: init out = x + bias, m = -inf, denom = 0 -------------
__global__ void k_init(const float* __restrict__ x,
                       const float* __restrict__ bias,
                       float* __restrict__ out, int Nn) {
    int i = blockIdx.x * blockDim.x + threadIdx.x;
    int total = Nn * HC;
    if (i < total) out[i] = x[i] + bias[i & (HC - 1)];
    if (i < Nn * NHEAD) { g_mmax[i] = 0x007FFFFFu; g_denom[i] = 0.f; }
}

// ---------------- K5: segment max over incoming edges ----------------------
__global__ void k_max(int Etot, int E) {
    int e = blockIdx.x * blockDim.x + threadIdx.x;
    if (e >= Etot) return;
    int s, d;
    if (e < E) { s = g_edges[e]; d = g_edges[E + e]; }
    else       { s = d = e - E; }
    float4 s0 = *(const float4*)&g_asrc[(size_t)s * NHEAD];
    float4 s1 = *(const float4*)&g_asrc[(size_t)s * NHEAD + 4];
    float4 d0 = *(const float4*)&g_adst[(size_t)d * NHEAD];
    float4 d1 = *(const float4*)&g_adst[(size_t)d * NHEAD + 4];
    float ev[8] = { s0.x + d0.x, s0.y + d0.y, s0.z + d0.z, s0.w + d0.w,
                    s1.x + d1.x, s1.y + d1.y, s1.z + d1.z, s1.w + d1.w };
#pragma unroll
    for (int h = 0; h < NHEAD; h++) {
        float v = ev[h];
        v = (v > 0.f) ? v : 0.2f * v;
        atomicMax(&g_mmax[(size_t)d * NHEAD + h], fenc(v));
    }
}

// ---------------- K6: exp(e - m), accumulate denominators -------------------
__global__ void k_exp(int Etot, int E) {
    int e = blockIdx.x * blockDim.x + threadIdx.x;
    if (e >= Etot) return;
    int s, d;
    if (e < E) { s = g_edges[e]; d = g_edges[E + e]; }
    else       { s = d = e - E; }
    float4 s0 = *(const float4*)&g_asrc[(size_t)s * NHEAD];
    float4 s1 = *(const float4*)&g_asrc[(size_t)s * NHEAD + 4];
    float4 d0 = *(const float4*)&g_adst[(size_t)d * NHEAD];
    float4 d1 = *(const float4*)&g_adst[(size_t)d * NHEAD + 4];
    float ev[8] = { s0.x + d0.x, s0.y + d0.y, s0.z + d0.z, s0.w + d0.w,
                    s1.x + d1.x, s1.y + d1.y, s1.z + d1.z, s1.w + d1.w };
    float exv[8];
#pragma unroll
    for (int h = 0; h < NHEAD; h++) {
        float v = ev[h];
        v = (v > 0.f) ? v : 0.2f * v;
        float m = fdec(g_mmax[(size_t)d * NHEAD + h]);
        float ex = __expf(v - m);
        exv[h] = ex;
        atomicAdd(&g_denom[(size_t)d * NHEAD + h], ex);
    }
    *(float4*)&g_ex[(size_t)e * NHEAD]     = make_float4(exv[0], exv[1], exv[2], exv[3]);
    *(float4*)&g_ex[(size_t)e * NHEAD + 4] = make_float4(exv[4], exv[5], exv[6], exv[7]);
}

// ---------------- K7: alpha + weighted scatter-add --------------------------
__global__ void k_agg(float* __restrict__ out, float* __restrict__ alpha_out,
                      int Etot, int E) {
    int w    = (blockIdx.x * blockDim.x + threadIdx.x) >> 5;
    int lane = threadIdx.x & 31;
    if (w >= Etot) return;
    int s, d;
    if (w < E) { s = g_edges[w]; d = g_edges[E + w]; }
    else       { s = d = w - E; }

    float alpha = 0.f;
    if (lane < NHEAD) {
        float ex = g_ex[(size_t)w * NHEAD + lane];
        float dn = g_denom[(size_t)d * NHEAD + lane];
        alpha = ex / (dn + 1e-16f);
        if (alpha_out) alpha_out[(size_t)w * NHEAD + lane] = alpha;
    }
#pragma unroll
    for (int j = 0; j < 2; j++) {
        int cb = j * 128 + lane * 4;        // channel base, covers [0,256)
        int h  = cb >> 5;                   // head of this float4
        float a = __shfl_sync(0xFFFFFFFFu, alpha, h);
        float4 v = *(const float4*)&g_xh[(size_t)s * HC + cb];
        float4 r = make_float4(v.x * a, v.y * a, v.z * a, v.w * a);
        float* p = &out[(size_t)d * HC + cb];
        asm volatile("red.global.add.v4.f32 [%0], {%1,%2,%3,%4};"
                     :: "l"(p), "f"(r.x), "f"(r.y), "f"(r.z), "f"(r.w)
                     : "memory");
    }
}

// ---------------- host launcher ---------------------------------------------
extern "C" void kernel_launch(void* const* d_in, const int* in_sizes, int n_in,
                              void* d_out, int out_size) {
    const float* x       = (const float*)d_in[0];
    const void*  ei      = d_in[1];
    const float* W       = (const float*)d_in[2];
    const float* att_src = (const float*)d_in[3];
    const float* att_dst = (const float*)d_in[4];
    const float* bias    = (const float*)d_in[5];

    int Nn   = in_sizes[0] / INC;
    int E    = in_sizes[1] / 2;
    int Etot = E + Nn;

    float* out = (float*)d_out;
    float* alpha_out = nullptr;
    if ((long long)out_size >= (long long)Nn * HC + (long long)Etot * NHEAD)
        alpha_out = out + (size_t)Nn * HC;

    // K0/K1: edge index width detection + conversion
    k_detect<<<1, 256>>>((const int*)ei, 16384);
    k_convert<<<(2 * E + 255) / 256, 256>>>(ei, 2 * E);

    // K2: projection GEMM
    dim3 ggrid((Nn + BM - 1) / BM, HC / BN);
    k_gemm<<<ggrid, 256>>>(x, W, Nn);

    // K3: per-node logits
    {
        int warps = Nn * NHEAD;
        k_logits<<<(warps * 32 + 255) / 256, 256>>>(att_src, att_dst, Nn);
    }

    // K4: init output (x + bias) and softmax state
    k_init<<<(Nn * HC + 255) / 256, 256>>>(x, bias, out, Nn);

    // K5/K6: segment softmax
    k_max<<<(Etot + 255) / 256, 256>>>(Etot, E);
    k_exp<<<(Etot + 255) / 256, 256>>>(Etot, E);

    // K7: alpha + aggregation
    {
        long long threads = (long long)Etot * 32;
        int blocks = (int)((threads + 255) / 256);
        k_agg<<<blocks, 256>>>(out, alpha_out, Etot, E);
    }
}

// round 2
// speedup vs baseline: 1.2098x; 1.2098x over previous
#include <cuda_runtime.h>
#include <cuda_bf16.h>

// Problem constants (fixed shapes from the reference)
#define NMAX 50000
#define EMAX 800000
#define INC  256
#define NHEAD 8
#define CH   32
#define HC   256   // NHEAD*CH

// ---------------- scratch (static device globals; no allocs allowed) -------
__device__ float    g_xh[NMAX * HC];            // projected features (N,H,C)
__device__ float    g_asrc[NMAX * NHEAD];       // per-node src logits
__device__ float    g_adst[NMAX * NHEAD];       // per-node dst logits
__device__ unsigned g_mmax[NMAX * NHEAD];       // encoded segment max
__device__ float    g_denom[NMAX * NHEAD];      // softmax denominators
__device__ int      g_edges[2 * EMAX];          // converted int32 edge index
__device__ float    g_ex[(EMAX + NMAX) * NHEAD];// exp(e - m) per edge
__device__ int      g_is64;

// ------------- float <-> orderable unsigned encoding for atomicMax ---------
__device__ __forceinline__ unsigned fenc(float f) {
    unsigned u = __float_as_uint(f);
    return (u & 0x80000000u) ? ~u : (u | 0x80000000u);
}
__device__ __forceinline__ float fdec(unsigned v) {
    return (v & 0x80000000u) ? __uint_as_float(v & 0x7FFFFFFFu)
                             : __uint_as_float(~v);
}

// ---------------- K0: detect int64 vs int32 edge_index ---------------------
__global__ void k_detect(const int* __restrict__ p, int n_words) {
    __shared__ int s;
    if (threadIdx.x == 0) s = 0;
    __syncthreads();
    int acc = 0;
    for (int i = 1 + 2 * (int)threadIdx.x; i < n_words; i += 2 * blockDim.x)
        acc |= p[i];
    if (acc) atomicOr(&s, 1);
    __syncthreads();
    if (threadIdx.x == 0) g_is64 = (s == 0) ? 1 : 0;
}

// ---------------- K1: convert edge index to int32 --------------------------
__global__ void k_convert(const void* __restrict__ p, int twoE) {
    int i = blockIdx.x * blockDim.x + threadIdx.x;
    if (i >= twoE) return;
    if (g_is64) g_edges[i] = (int)((const long long*)p)[i];
    else        g_edges[i] = ((const int*)p)[i];
}

// ---------------- MMA helpers ----------------------------------------------
__device__ __forceinline__ void ldsm4(unsigned r[4], const void* p) {
    unsigned a = (unsigned)__cvta_generic_to_shared(p);
    asm volatile("ldmatrix.sync.aligned.m8n8.x4.shared.b16 {%0,%1,%2,%3}, [%4];"
                 : "=r"(r[0]), "=r"(r[1]), "=r"(r[2]), "=r"(r[3]) : "r"(a));
}
__device__ __forceinline__ void ldsm4t(unsigned r[4], const void* p) {
    unsigned a = (unsigned)__cvta_generic_to_shared(p);
    asm volatile("ldmatrix.sync.aligned.m8n8.x4.trans.shared.b16 {%0,%1,%2,%3}, [%4];"
                 : "=r"(r[0]), "=r"(r[1]), "=r"(r[2]), "=r"(r[3]) : "r"(a));
}
__device__ __forceinline__ void mma16816(float c[4], const unsigned a[4],
                                         unsigned b0, unsigned b1) {
    asm volatile(
        "mma.sync.aligned.m16n8k16.row.col.f32.bf16.bf16.f32 "
        "{%0,%1,%2,%3}, {%4,%5,%6,%7}, {%8,%9}, {%0,%1,%2,%3};"
        : "+f"(c[0]), "+f"(c[1]), "+f"(c[2]), "+f"(c[3])
        : "r"(a[0]), "r"(a[1]), "r"(a[2]), "r"(a[3]), "r"(b0), "r"(b1));
}
__device__ __forceinline__ void split_bf16(float v, __nv_bfloat16& h, __nv_bfloat16& l) {
    h = __float2bfloat16(v);
    l = __float2bfloat16(v - __bfloat162float(h));
}

// ---------------- K2: xh = x @ W  via bf16 hi/lo split tensor-core MMA -----
// Block tile: 128(M) x 64(N), BK=32. 8 warps (4x2), warp tile 32x32.
// acc = Ah*Bh + Ah*Bl + Al*Bh  (error ~2^-17 relative, effectively fp32)
#define GBM 128
#define GBN 64
#define GBK 32
__global__ __launch_bounds__(256, 2) void k_gemm(const float* __restrict__ A,
                                                 const float* __restrict__ B,
                                                 int Nn) {
    __shared__ __nv_bfloat16 sAh[GBM][40];   // pad to 40 -> conflict-free ldsm
    __shared__ __nv_bfloat16 sAl[GBM][40];
    __shared__ __nv_bfloat16 sBh[GBK][72];   // pad to 72 -> conflict-free ldsm.trans
    __shared__ __nv_bfloat16 sBl[GBK][72];

    int tid  = threadIdx.x;
    int lane = tid & 31;
    int warp = tid >> 5;
    int wm = warp & 3, wn = warp >> 2;
    int brow = blockIdx.x * GBM;
    int bcol = blockIdx.y * GBN;

    float acc[2][4][4];
#pragma unroll
    for (int i = 0; i < 2; i++)
#pragma unroll
        for (int j = 0; j < 4; j++)
#pragma unroll
            for (int k = 0; k < 4; k++) acc[i][j][k] = 0.f;

    // loader coordinates
    int ar  = tid >> 1;            // 0..127 (A row)
    int ac  = (tid & 1) * 16;      // col half
    int agr = brow + ar;
    int brr = tid >> 3;            // 0..31  (B row)
    int bcc = (tid & 7) * 8;       // col base

    for (int k0 = 0; k0 < INC; k0 += GBK) {
        if (k0) __syncthreads();
        // load + split A tile (128 x 32 fp32 -> bf16 hi/lo)
#pragma unroll
        for (int q = 0; q < 4; q++) {
            float4 v = make_float4(0.f, 0.f, 0.f, 0.f);
            if (agr < Nn) v = *(const float4*)&A[(size_t)agr * INC + k0 + ac + q * 4];
            float vs[4] = {v.x, v.y, v.z, v.w};
#pragma unroll
            for (int u = 0; u < 4; u += 2) {
                __nv_bfloat16 h0, l0, h1, l1;
                split_bf16(vs[u], h0, l0);
                split_bf16(vs[u + 1], h1, l1);
                *(__nv_bfloat162*)&sAh[ar][ac + q * 4 + u] = __nv_bfloat162(h0, h1);
                *(__nv_bfloat162*)&sAl[ar][ac + q * 4 + u] = __nv_bfloat162(l0, l1);
            }
        }
        // load + split B tile (32 x 64)
#pragma unroll
        for (int q = 0; q < 2; q++) {
            float4 v = *(const float4*)&B[(size_t)(k0 + brr) * HC + bcol + bcc + q * 4];
            float vs[4] = {v.x, v.y, v.z, v.w};
#pragma unroll
            for (int u = 0; u < 4; u += 2) {
                __nv_bfloat16 h0, l0, h1, l1;
                split_bf16(vs[u], h0, l0);
                split_bf16(vs[u + 1], h1, l1);
                *(__nv_bfloat162*)&sBh[brr][bcc + q * 4 + u] = __nv_bfloat162(h0, h1);
                *(__nv_bfloat162*)&sBl[brr][bcc + q * 4 + u] = __nv_bfloat162(l0, l1);
            }
        }
        __syncthreads();

#pragma unroll
        for (int ks = 0; ks < 2; ks++) {
            unsigned Ah[2][4], Al[2][4], Bh[2][4], Bl[2][4];
            int akk = ks * 16 + (lane >> 4) * 8;
#pragma unroll
            for (int mt = 0; mt < 2; mt++) {
                int r = wm * 32 + mt * 16 + (lane & 15);
                ldsm4(Ah[mt], &sAh[r][akk]);
                ldsm4(Al[mt], &sAl[r][akk]);
            }
            int bkr = ks * 16 + ((lane >> 3) & 1) * 8 + (lane & 7);
#pragma unroll
            for (int p = 0; p < 2; p++) {
                int bnc = wn * 32 + p * 16 + (lane >> 4) * 8;
                ldsm4t(Bh[p], &sBh[bkr][bnc]);
                ldsm4t(Bl[p], &sBl[bkr][bnc]);
            }
#pragma unroll
            for (int mt = 0; mt < 2; mt++)
#pragma unroll
                for (int nt = 0; nt < 4; nt++) {
                    int p = nt >> 1, i0 = (nt & 1) * 2;
                    mma16816(acc[mt][nt], Ah[mt], Bh[p][i0], Bh[p][i0 + 1]);
                    mma16816(acc[mt][nt], Ah[mt], Bl[p][i0], Bl[p][i0 + 1]);
                    mma16816(acc[mt][nt], Al[mt], Bh[p][i0], Bh[p][i0 + 1]);
                }
        }
    }

    // epilogue: write fragments to g_xh
#pragma unroll
    for (int mt = 0; mt < 2; mt++) {
        int r0 = brow + wm * 32 + mt * 16 + (lane >> 2);
#pragma unroll
        for (int nt = 0; nt < 4; nt++) {
            int c = bcol + wn * 32 + nt * 8 + (lane & 3) * 2;
            if (r0 < Nn)
                *(float2*)&g_xh[(size_t)r0 * HC + c] =
                    make_float2(acc[mt][nt][0], acc[mt][nt][1]);
            if (r0 + 8 < Nn)
                *(float2*)&g_xh[(size_t)(r0 + 8) * HC + c] =
                    make_float2(acc[mt][nt][2], acc[mt][nt][3]);
        }
    }
}

// ---------------- K3: per-node attention logits (warp per node) ------------
__global__ void k_logits(const float* __restrict__ att_src,
                         const float* __restrict__ att_dst, int Nn) {
    int w    = (blockIdx.x * blockDim.x + threadIdx.x) >> 5;
    int lane = threadIdx.x & 31;
    if (w >= Nn) return;
    int cb = lane * 8;                       // channels [cb, cb+8), head = lane>>2
    float4 v0 = *(const float4*)&g_xh[(size_t)w * HC + cb];
    float4 v1 = *(const float4*)&g_xh[(size_t)w * HC + cb + 4];
    float4 s0 = *(const float4*)&att_src[cb];
    float4 s1 = *(const float4*)&att_src[cb + 4];
    float4 d0 = *(const float4*)&att_dst[cb];
    float4 d1 = *(const float4*)&att_dst[cb + 4];
    float s = v0.x * s0.x + v0.y * s0.y + v0.z * s0.z + v0.w * s0.w
            + v1.x * s1.x + v1.y * s1.y + v1.z * s1.z + v1.w * s1.w;
    float d = v0.x * d0.x + v0.y * d0.y + v0.z * d0.z + v0.w * d0.w
            + v1.x * d1.x + v1.y * d1.y + v1.z * d1.z + v1.w * d1.w;
    s += __shfl_xor_sync(0xFFFFFFFFu, s, 1);
    s += __shfl_xor_sync(0xFFFFFFFFu, s, 2);
    d += __shfl_xor_sync(0xFFFFFFFFu, d, 1);
    d += __shfl_xor_sync(0xFFFFFFFFu, d, 2);
    if ((lane & 3) == 0) {
        g_asrc[w * NHEAD + (lane >> 2)] = s;
        g_adst[w * NHEAD + (lane >> 2)] = d;
    }
}

// ---------------- K4: init out = x + bias, m = -inf, denom = 0 -------------
__global__ void k_init(const float* __restrict__ x,
                       const float* __restrict__ bias,
                       float* __restrict__ out, int Nn) {
    int i = blockIdx.x * blockDim.x + threadIdx.x;
    int total = Nn * HC;
    if (i < total) out[i] = x[i] + bias[i & (HC - 1)];
    if (i < Nn * NHEAD) { g_mmax[i] = 0x007FFFFFu; g_denom[i] = 0.f; }
}

// ---------------- K5: segment max over incoming edges ----------------------
__global__ void k_max(int Etot, int E) {
    int e = blockIdx.x * blockDim.x + threadIdx.x;
    if (e >= Etot) return;
    int s, d;
    if (e < E) { s = g_edges[e]; d = g_edges[E + e]; }
    else       { s = d = e - E; }
    float4 s0 = *(const float4*)&g_asrc[(size_t)s * NHEAD];
    float4 s1 = *(const float4*)&g_asrc[(size_t)s * NHEAD + 4];
    float4 d0 = *(const float4*)&g_adst[(size_t)d * NHEAD];
    float4 d1 = *(const float4*)&g_adst[(size_t)d * NHEAD + 4];
    float ev[8] = { s0.x + d0.x, s0.y + d0.y, s0.z + d0.z, s0.w + d0.w,
                    s1.x + d1.x, s1.y + d1.y, s1.z + d1.z, s1.w + d1.w };
#pragma unroll
    for (int h = 0; h < NHEAD; h++) {
        float v = ev[h];
        v = (v > 0.f) ? v : 0.2f * v;
        atomicMax(&g_mmax[(size_t)d * NHEAD + h], fenc(v));
    }
}

// ---------------- K6: exp(e - m), accumulate denominators -------------------
__global__ void k_exp(int Etot, int E) {
    int e = blockIdx.x * blockDim.x + threadIdx.x;
    if (e >= Etot) return;
    int s, d;
    if (e < E) { s = g_edges[e]; d = g_edges[E + e]; }
    else       { s = d = e - E; }
    float4 s0 = *(const float4*)&g_asrc[(size_t)s * NHEAD];
    float4 s1 = *(const float4*)&g_asrc[(size_t)s * NHEAD + 4];
    float4 d0 = *(const float4*)&g_adst[(size_t)d * NHEAD];
    float4 d1 = *(const float4*)&g_adst[(size_t)d * NHEAD + 4];
    float ev[8] = { s0.x + d0.x, s0.y + d0.y, s0.z + d0.z, s0.w + d0.w,
                    s1.x + d1.x, s1.y + d1.y, s1.z + d1.z, s1.w + d1.w };
    float exv[8];
#pragma unroll
    for (int h = 0; h < NHEAD; h++) {
        float v = ev[h];
        v = (v > 0.f) ? v : 0.2f * v;
        float m = fdec(g_mmax[(size_t)d * NHEAD + h]);
        float ex = __expf(v - m);
        exv[h] = ex;
        atomicAdd(&g_denom[(size_t)d * NHEAD + h], ex);
    }
    *(float4*)&g_ex[(size_t)e * NHEAD]     = make_float4(exv[0], exv[1], exv[2], exv[3]);
    *(float4*)&g_ex[(size_t)e * NHEAD + 4] = make_float4(exv[4], exv[5], exv[6], exv[7]);
}

// ---------------- K7: alpha + weighted scatter-add --------------------------
__global__ void k_agg(float* __restrict__ out, float* __restrict__ alpha_out,
                      int Etot, int E) {
    int w    = (blockIdx.x * blockDim.x + threadIdx.x) >> 5;
    int lane = threadIdx.x & 31;
    if (w >= Etot) return;
    int s, d;
    if (w < E) { s = g_edges[w]; d = g_edges[E + w]; }
    else       { s = d = w - E; }

    float alpha = 0.f;
    if (lane < NHEAD) {
        float ex = g_ex[(size_t)w * NHEAD + lane];
        float dn = g_denom[(size_t)d * NHEAD + lane];
        alpha = ex / (dn + 1e-16f);
        if (alpha_out) alpha_out[(size_t)w * NHEAD + lane] = alpha;
    }
#pragma unroll
    for (int j = 0; j < 2; j++) {
        int cb = j * 128 + lane * 4;        // channel base, covers [0,256)
        int h  = cb >> 5;                   // head of this float4
        float a = __shfl_sync(0xFFFFFFFFu, alpha, h);
        float4 v = *(const float4*)&g_xh[(size_t)s * HC + cb];
        float4 r = make_float4(v.x * a, v.y * a, v.z * a, v.w * a);
        float* p = &out[(size_t)d * HC + cb];
        asm volatile("red.global.add.v4.f32 [%0], {%1,%2,%3,%4};"
                     :: "l"(p), "f"(r.x), "f"(r.y), "f"(r.z), "f"(r.w)
                     : "memory");
    }
}

// ---------------- host launcher ---------------------------------------------
extern "C" void kernel_launch(void* const* d_in, const int* in_sizes, int n_in,
                              void* d_out, int out_size) {
    const float* x       = (const float*)d_in[0];
    const void*  ei      = d_in[1];
    const float* W       = (const float*)d_in[2];
    const float* att_src = (const float*)d_in[3];
    const float* att_dst = (const float*)d_in[4];
    const float* bias    = (const float*)d_in[5];

    int Nn   = in_sizes[0] / INC;
    int E    = in_sizes[1] / 2;
    int Etot = E + Nn;

    float* out = (float*)d_out;
    float* alpha_out = nullptr;
    if ((long long)out_size >= (long long)Nn * HC + (long long)Etot * NHEAD)
        alpha_out = out + (size_t)Nn * HC;

    // K0/K1: edge index width detection + conversion
    k_detect<<<1, 256>>>((const int*)ei, 16384);
    k_convert<<<(2 * E + 255) / 256, 256>>>(ei, 2 * E);

    // K2: projection GEMM (bf16 split tensor cores)
    dim3 ggrid((Nn + GBM - 1) / GBM, HC / GBN);
    k_gemm<<<ggrid, 256>>>(x, W, Nn);

    // K3: per-node logits (warp per node)
    k_logits<<<(Nn * 32 + 255) / 256, 256>>>(att_src, att_dst, Nn);

    // K4: init output (x + bias) and softmax state
    k_init<<<(Nn * HC + 255) / 256, 256>>>(x, bias, out, Nn);

    // K5/K6: segment softmax
    k_max<<<(Etot + 255) / 256, 256>>>(Etot, E);
    k_exp<<<(Etot + 255) / 256, 256>>>(Etot, E);

    // K7: alpha + aggregation
    {
        long long threads = (long long)Etot * 32;
        int blocks = (int)((threads + 255) / 256);
        k_agg<<<blocks, 256>>>(out, alpha_out, Etot, E);
    }
}

// round 3
// speedup vs baseline: 1.7457x; 1.4429x over previous
#include <cuda_runtime.h>
#include <cuda_bf16.h>

// Problem constants (fixed shapes from the reference)
#define NMAX 50000
#define EMAX 800000
#define INC  256
#define NHEAD 8
#define CH   32
#define HC   256   // NHEAD*CH

// ---------------- scratch (static device globals; no allocs allowed) -------
__device__ float    g_xh[NMAX * HC];            // projected features (N,H,C)
__device__ float    g_asrc[NMAX * NHEAD];       // per-node src logits
__device__ float    g_adst[NMAX * NHEAD];       // per-node dst logits
__device__ float    g_denom[NMAX * NHEAD];      // softmax denominators
__device__ int      g_edges[2 * EMAX];          // converted int32 edge index
__device__ int      g_cnt[NMAX];                // in-degree histogram
__device__ int      g_fill[NMAX];               // scatter fill counters
__device__ int      g_off[NMAX + 1];            // CSR offsets
__device__ int      g_ssrc[EMAX];               // src node per dst-sorted edge
__device__ int      g_is64;

// ---------------- K0: detect int64 vs int32 edge_index ---------------------
__global__ void k_detect(const int* __restrict__ p, int n_words) {
    __shared__ int s;
    if (threadIdx.x == 0) s = 0;
    __syncthreads();
    int acc = 0;
    for (int i = 1 + 2 * (int)threadIdx.x; i < n_words; i += 2 * blockDim.x)
        acc |= p[i];
    if (acc) atomicOr(&s, 1);
    __syncthreads();
    if (threadIdx.x == 0) g_is64 = (s == 0) ? 1 : 0;
}

// ---------------- K0b: zero histogram + fill counters ----------------------
__global__ void k_zero(int Nn) {
    int i = blockIdx.x * blockDim.x + threadIdx.x;
    if (i < Nn) { g_cnt[i] = 0; g_fill[i] = 0; }
}

// ---------------- K1: convert edge index to int32 + dst histogram ----------
__global__ void k_convert(const void* __restrict__ p, int twoE, int E) {
    int i = blockIdx.x * blockDim.x + threadIdx.x;
    if (i >= twoE) return;
    int v;
    if (g_is64) v = (int)((const long long*)p)[i];
    else        v = ((const int*)p)[i];
    g_edges[i] = v;
    if (i >= E) atomicAdd(&g_cnt[v], 1);   // dst half -> in-degree histogram
}

// ---------------- MMA helpers ----------------------------------------------
__device__ __forceinline__ void ldsm4(unsigned r[4], const void* p) {
    unsigned a = (unsigned)__cvta_generic_to_shared(p);
    asm volatile("ldmatrix.sync.aligned.m8n8.x4.shared.b16 {%0,%1,%2,%3}, [%4];"
                 : "=r"(r[0]), "=r"(r[1]), "=r"(r[2]), "=r"(r[3]) : "r"(a));
}
__device__ __forceinline__ void ldsm4t(unsigned r[4], const void* p) {
    unsigned a = (unsigned)__cvta_generic_to_shared(p);
    asm volatile("ldmatrix.sync.aligned.m8n8.x4.trans.shared.b16 {%0,%1,%2,%3}, [%4];"
                 : "=r"(r[0]), "=r"(r[1]), "=r"(r[2]), "=r"(r[3]) : "r"(a));
}
__device__ __forceinline__ void mma16816(float c[4], const unsigned a[4],
                                         unsigned b0, unsigned b1) {
    asm volatile(
        "mma.sync.aligned.m16n8k16.row.col.f32.bf16.bf16.f32 "
        "{%0,%1,%2,%3}, {%4,%5,%6,%7}, {%8,%9}, {%0,%1,%2,%3};"
        : "+f"(c[0]), "+f"(c[1]), "+f"(c[2]), "+f"(c[3])
        : "r"(a[0]), "r"(a[1]), "r"(a[2]), "r"(a[3]), "r"(b0), "r"(b1));
}
__device__ __forceinline__ void split_bf16(float v, __nv_bfloat16& h, __nv_bfloat16& l) {
    h = __float2bfloat16(v);
    l = __float2bfloat16(v - __bfloat162float(h));
}

// ---------------- K2: xh = x @ W  via bf16 hi/lo split tensor-core MMA -----
#define GBM 128
#define GBN 64
#define GBK 32
__global__ __launch_bounds__(256, 2) void k_gemm(const float* __restrict__ A,
                                                 const float* __restrict__ B,
                                                 int Nn) {
    __shared__ __nv_bfloat16 sAh[GBM][40];
    __shared__ __nv_bfloat16 sAl[GBM][40];
    __shared__ __nv_bfloat16 sBh[GBK][72];
    __shared__ __nv_bfloat16 sBl[GBK][72];

    int tid  = threadIdx.x;
    int lane = tid & 31;
    int warp = tid >> 5;
    int wm = warp & 3, wn = warp >> 2;
    int brow = blockIdx.x * GBM;
    int bcol = blockIdx.y * GBN;

    float acc[2][4][4];
#pragma unroll
    for (int i = 0; i < 2; i++)
#pragma unroll
        for (int j = 0; j < 4; j++)
#pragma unroll
            for (int k = 0; k < 4; k++) acc[i][j][k] = 0.f;

    int ar  = tid >> 1;
    int ac  = (tid & 1) * 16;
    int agr = brow + ar;
    int brr = tid >> 3;
    int bcc = (tid & 7) * 8;

    for (int k0 = 0; k0 < INC; k0 += GBK) {
        if (k0) __syncthreads();
#pragma unroll
        for (int q = 0; q < 4; q++) {
            float4 v = make_float4(0.f, 0.f, 0.f, 0.f);
            if (agr < Nn) v = *(const float4*)&A[(size_t)agr * INC + k0 + ac + q * 4];
            float vs[4] = {v.x, v.y, v.z, v.w};
#pragma unroll
            for (int u = 0; u < 4; u += 2) {
                __nv_bfloat16 h0, l0, h1, l1;
                split_bf16(vs[u], h0, l0);
                split_bf16(vs[u + 1], h1, l1);
                *(__nv_bfloat162*)&sAh[ar][ac + q * 4 + u] = __nv_bfloat162(h0, h1);
                *(__nv_bfloat162*)&sAl[ar][ac + q * 4 + u] = __nv_bfloat162(l0, l1);
            }
        }
#pragma unroll
        for (int q = 0; q < 2; q++) {
            float4 v = *(const float4*)&B[(size_t)(k0 + brr) * HC + bcol + bcc + q * 4];
            float vs[4] = {v.x, v.y, v.z, v.w};
#pragma unroll
            for (int u = 0; u < 4; u += 2) {
                __nv_bfloat16 h0, l0, h1, l1;
                split_bf16(vs[u], h0, l0);
                split_bf16(vs[u + 1], h1, l1);
                *(__nv_bfloat162*)&sBh[brr][bcc + q * 4 + u] = __nv_bfloat162(h0, h1);
                *(__nv_bfloat162*)&sBl[brr][bcc + q * 4 + u] = __nv_bfloat162(l0, l1);
            }
        }
        __syncthreads();

#pragma unroll
        for (int ks = 0; ks < 2; ks++) {
            unsigned Ah[2][4], Al[2][4], Bh[2][4], Bl[2][4];
            int akk = ks * 16 + (lane >> 4) * 8;
#pragma unroll
            for (int mt = 0; mt < 2; mt++) {
                int r = wm * 32 + mt * 16 + (lane & 15);
                ldsm4(Ah[mt], &sAh[r][akk]);
                ldsm4(Al[mt], &sAl[r][akk]);
            }
            int bkr = ks * 16 + ((lane >> 3) & 1) * 8 + (lane & 7);
#pragma unroll
            for (int p = 0; p < 2; p++) {
                int bnc = wn * 32 + p * 16 + (lane >> 4) * 8;
                ldsm4t(Bh[p], &sBh[bkr][bnc]);
                ldsm4t(Bl[p], &sBl[bkr][bnc]);
            }
#pragma unroll
            for (int mt = 0; mt < 2; mt++)
#pragma unroll
                for (int nt = 0; nt < 4; nt++) {
                    int p = nt >> 1, i0 = (nt & 1) * 2;
                    mma16816(acc[mt][nt], Ah[mt], Bh[p][i0], Bh[p][i0 + 1]);
                    mma16816(acc[mt][nt], Ah[mt], Bl[p][i0], Bl[p][i0 + 1]);
                    mma16816(acc[mt][nt], Al[mt], Bh[p][i0], Bh[p][i0 + 1]);
                }
        }
    }

#pragma unroll
    for (int mt = 0; mt < 2; mt++) {
        int r0 = brow + wm * 32 + mt * 16 + (lane >> 2);
#pragma unroll
        for (int nt = 0; nt < 4; nt++) {
            int c = bcol + wn * 32 + nt * 8 + (lane & 3) * 2;
            if (r0 < Nn)
                *(float2*)&g_xh[(size_t)r0 * HC + c] =
                    make_float2(acc[mt][nt][0], acc[mt][nt][1]);
            if (r0 + 8 < Nn)
                *(float2*)&g_xh[(size_t)(r0 + 8) * HC + c] =
                    make_float2(acc[mt][nt][2], acc[mt][nt][3]);
        }
    }
}

// ---------------- K3: per-node attention logits (warp per node) ------------
__global__ void k_logits(const float* __restrict__ att_src,
                         const float* __restrict__ att_dst, int Nn) {
    int w    = (blockIdx.x * blockDim.x + threadIdx.x) >> 5;
    int lane = threadIdx.x & 31;
    if (w >= Nn) return;
    int cb = lane * 8;
    float4 v0 = *(const float4*)&g_xh[(size_t)w * HC + cb];
    float4 v1 = *(const float4*)&g_xh[(size_t)w * HC + cb + 4];
    float4 s0 = *(const float4*)&att_src[cb];
    float4 s1 = *(const float4*)&att_src[cb + 4];
    float4 d0 = *(const float4*)&att_dst[cb];
    float4 d1 = *(const float4*)&att_dst[cb + 4];
    float s = v0.x * s0.x + v0.y * s0.y + v0.z * s0.z + v0.w * s0.w
            + v1.x * s1.x + v1.y * s1.y + v1.z * s1.z + v1.w * s1.w;
    float d = v0.x * d0.x + v0.y * d0.y + v0.z * d0.z + v0.w * d0.w
            + v1.x * d1.x + v1.y * d1.y + v1.z * d1.z + v1.w * d1.w;
    s += __shfl_xor_sync(0xFFFFFFFFu, s, 1);
    s += __shfl_xor_sync(0xFFFFFFFFu, s, 2);
    d += __shfl_xor_sync(0xFFFFFFFFu, d, 1);
    d += __shfl_xor_sync(0xFFFFFFFFu, d, 2);
    if ((lane & 3) == 0) {
        g_asrc[w * NHEAD + (lane >> 2)] = s;
        g_adst[w * NHEAD + (lane >> 2)] = d;
    }
}

// ---------------- K4: single-block chunked exclusive scan -> CSR offsets ---
__global__ void k_scan(int Nn) {
    __shared__ int sm[1024];
    __shared__ int carry;
    if (threadIdx.x == 0) { carry = 0; g_off[0] = 0; }
    __syncthreads();
    for (int base = 0; base < Nn; base += 1024) {
        int i = base + (int)threadIdx.x;
        int v = (i < Nn) ? g_cnt[i] : 0;
        sm[threadIdx.x] = v;
        __syncthreads();
        for (int o = 1; o < 1024; o <<= 1) {
            int t = (threadIdx.x >= (unsigned)o) ? sm[threadIdx.x - o] : 0;
            __syncthreads();
            sm[threadIdx.x] += t;
            __syncthreads();
        }
        if (i < Nn) g_off[i + 1] = carry + sm[threadIdx.x];
        __syncthreads();
        if (threadIdx.x == 0) carry += sm[1023];
        __syncthreads();
    }
}

// ---------------- K5: scatter edges into dst-sorted order ------------------
__global__ void k_scatter(int E) {
    int e = blockIdx.x * blockDim.x + threadIdx.x;
    if (e >= E) return;
    int s = g_edges[e];
    int d = g_edges[E + e];
    int pos = g_off[d] + atomicAdd(&g_fill[d], 1);
    g_ssrc[pos] = s;
}

// ---------------- K6: warp-per-node softmax + aggregation (no atomics) -----
__global__ __launch_bounds__(256) void k_agg(const float* __restrict__ x,
                                             const float* __restrict__ bias,
                                             float* __restrict__ out, int Nn) {
    int d    = (blockIdx.x * blockDim.x + threadIdx.x) >> 5;
    int lane = threadIdx.x & 31;
    if (d >= Nn) return;
    int h  = lane >> 2;        // head for this lane's 8 channels
    int cb = lane * 8;         // channel base

    float adst_h = g_adst[d * NHEAD + h];

    // self loop contribution
    float e0 = g_asrc[d * NHEAD + h] + adst_h;
    e0 = (e0 > 0.f) ? e0 : 0.2f * e0;
    float ex = __expf(e0);
    float dn = ex;
    float4 v0 = *(const float4*)&g_xh[(size_t)d * HC + cb];
    float4 v1 = *(const float4*)&g_xh[(size_t)d * HC + cb + 4];
    float a0 = ex * v0.x, a1 = ex * v0.y, a2 = ex * v0.z, a3 = ex * v0.w;
    float a4 = ex * v1.x, a5 = ex * v1.y, a6 = ex * v1.z, a7 = ex * v1.w;

    int beg = g_off[d], end = g_off[d + 1];
#pragma unroll 2
    for (int j = beg; j < end; j++) {
        int s = g_ssrc[j];
        float e = g_asrc[s * NHEAD + h] + adst_h;
        e = (e > 0.f) ? e : 0.2f * e;
        float w = __expf(e);
        dn += w;
        float4 u0 = *(const float4*)&g_xh[(size_t)s * HC + cb];
        float4 u1 = *(const float4*)&g_xh[(size_t)s * HC + cb + 4];
        a0 += w * u0.x; a1 += w * u0.y; a2 += w * u0.z; a3 += w * u0.w;
        a4 += w * u1.x; a5 += w * u1.y; a6 += w * u1.z; a7 += w * u1.w;
    }

    float inv = 1.f / (dn + 1e-16f);
    float4 xb0 = *(const float4*)&x[(size_t)d * HC + cb];
    float4 xb1 = *(const float4*)&x[(size_t)d * HC + cb + 4];
    float4 b0  = *(const float4*)&bias[cb];
    float4 b1  = *(const float4*)&bias[cb + 4];
    float4 o0 = make_float4(a0 * inv + xb0.x + b0.x, a1 * inv + xb0.y + b0.y,
                            a2 * inv + xb0.z + b0.z, a3 * inv + xb0.w + b0.w);
    float4 o1 = make_float4(a4 * inv + xb1.x + b1.x, a5 * inv + xb1.y + b1.y,
                            a6 * inv + xb1.z + b1.z, a7 * inv + xb1.w + b1.w);
    *(float4*)&out[(size_t)d * HC + cb]     = o0;
    *(float4*)&out[(size_t)d * HC + cb + 4] = o1;
    if ((lane & 3) == 0) g_denom[d * NHEAD + h] = dn;
}

// ---------------- K7: per-edge alpha output ---------------------------------
__global__ void k_alpha(float* __restrict__ alpha_out, int Etot, int E) {
    int e = blockIdx.x * blockDim.x + threadIdx.x;
    if (e >= Etot) return;
    int s, d;
    if (e < E) { s = g_edges[e]; d = g_edges[E + e]; }
    else       { s = d = e - E; }
    float4 s0 = *(const float4*)&g_asrc[(size_t)s * NHEAD];
    float4 s1 = *(const float4*)&g_asrc[(size_t)s * NHEAD + 4];
    float4 d0 = *(const float4*)&g_adst[(size_t)d * NHEAD];
    float4 d1 = *(const float4*)&g_adst[(size_t)d * NHEAD + 4];
    float4 n0 = *(const float4*)&g_denom[(size_t)d * NHEAD];
    float4 n1 = *(const float4*)&g_denom[(size_t)d * NHEAD + 4];
    float ev[8] = { s0.x + d0.x, s0.y + d0.y, s0.z + d0.z, s0.w + d0.w,
                    s1.x + d1.x, s1.y + d1.y, s1.z + d1.z, s1.w + d1.w };
    float dns[8] = { n0.x, n0.y, n0.z, n0.w, n1.x, n1.y, n1.z, n1.w };
    float al[8];
#pragma unroll
    for (int h = 0; h < NHEAD; h++) {
        float v = ev[h];
        v = (v > 0.f) ? v : 0.2f * v;
        al[h] = __expf(v) / (dns[h] + 1e-16f);
    }
    *(float4*)&alpha_out[(size_t)e * NHEAD]     = make_float4(al[0], al[1], al[2], al[3]);
    *(float4*)&alpha_out[(size_t)e * NHEAD + 4] = make_float4(al[4], al[5], al[6], al[7]);
}

// ---------------- host launcher ---------------------------------------------
extern "C" void kernel_launch(void* const* d_in, const int* in_sizes, int n_in,
                              void* d_out, int out_size) {
    const float* x       = (const float*)d_in[0];
    const void*  ei      = d_in[1];
    const float* W       = (const float*)d_in[2];
    const float* att_src = (const float*)d_in[3];
    const float* att_dst = (const float*)d_in[4];
    const float* bias    = (const float*)d_in[5];

    int Nn   = in_sizes[0] / INC;
    int E    = in_sizes[1] / 2;
    int Etot = E + Nn;

    float* out = (float*)d_out;
    float* alpha_out = nullptr;
    if ((long long)out_size >= (long long)Nn * HC + (long long)Etot * NHEAD)
        alpha_out = out + (size_t)Nn * HC;

    // edge index conversion + CSR build
    k_detect<<<1, 256>>>((const int*)ei, 16384);
    k_zero<<<(Nn + 255) / 256, 256>>>(Nn);
    k_convert<<<(2 * E + 255) / 256, 256>>>(ei, 2 * E, E);

    // projection GEMM (independent of edges)
    dim3 ggrid((Nn + GBM - 1) / GBM, HC / GBN);
    k_gemm<<<ggrid, 256>>>(x, W, Nn);
    k_logits<<<(Nn * 32 + 255) / 256, 256>>>(att_src, att_dst, Nn);

    // CSR offsets + dst-sorted edge list
    k_scan<<<1, 1024>>>(Nn);
    k_scatter<<<(E + 255) / 256, 256>>>(E);

    // fused softmax + aggregation + residual + bias (no atomics)
    k_agg<<<(Nn * 32 + 255) / 256, 256>>>(x, bias, out, Nn);

    // alpha output
    if (alpha_out)
        k_alpha<<<(Etot + 255) / 256, 256>>>(alpha_out, Etot, E);
}

// round 4
// speedup vs baseline: 2.1115x; 1.2095x over previous
#include <cuda_runtime.h>
#include <cuda_bf16.h>

// Problem constants (fixed shapes from the reference)
#define NMAX 50000
#define EMAX 800000
#define INC  256
#define NHEAD 8
#define CH   32
#define HC   256   // NHEAD*CH

// ---------------- scratch (static device globals; no allocs allowed) -------
__device__ float    g_xh[NMAX * HC];            // projected features (N,H,C)
__device__ float    g_asrc[NMAX * NHEAD];       // per-node src logits
__device__ float    g_adst[NMAX * NHEAD];       // per-node dst logits
__device__ float    g_denom[NMAX * NHEAD];      // softmax denominators
__device__ int      g_edges[2 * EMAX];          // converted int32 edge index
__device__ int      g_cnt[NMAX];                // in-degree histogram
__device__ int      g_fill[NMAX];               // scatter fill counters
__device__ int      g_off[NMAX + 1];            // CSR offsets
__device__ int      g_ssrc[EMAX];               // src node per dst-sorted edge
__device__ int      g_is64;

// ---------------- K0: detect int64 vs int32 edge_index ---------------------
__global__ void k_detect(const int* __restrict__ p, int n_words) {
    __shared__ int s;
    if (threadIdx.x == 0) s = 0;
    __syncthreads();
    int acc = 0;
    for (int i = 1 + 2 * (int)threadIdx.x; i < n_words; i += 2 * blockDim.x)
        acc |= p[i];
    if (acc) atomicOr(&s, 1);
    __syncthreads();
    if (threadIdx.x == 0) g_is64 = (s == 0) ? 1 : 0;
}

// ---------------- K0b: zero histogram + fill counters ----------------------
__global__ void k_zero(int Nn) {
    int i = blockIdx.x * blockDim.x + threadIdx.x;
    if (i < Nn) { g_cnt[i] = 0; g_fill[i] = 0; }
}

// ---------------- K1: convert edge index to int32 + dst histogram ----------
__global__ void k_convert(const void* __restrict__ p, int twoE, int E) {
    int i = blockIdx.x * blockDim.x + threadIdx.x;
    if (i >= twoE) return;
    int v;
    if (g_is64) v = (int)((const long long*)p)[i];
    else        v = ((const int*)p)[i];
    g_edges[i] = v;
    if (i >= E) atomicAdd(&g_cnt[v], 1);   // dst half -> in-degree histogram
}

// ---------------- MMA helpers ----------------------------------------------
__device__ __forceinline__ void ldsm4(unsigned r[4], const void* p) {
    unsigned a = (unsigned)__cvta_generic_to_shared(p);
    asm volatile("ldmatrix.sync.aligned.m8n8.x4.shared.b16 {%0,%1,%2,%3}, [%4];"
                 : "=r"(r[0]), "=r"(r[1]), "=r"(r[2]), "=r"(r[3]) : "r"(a));
}
__device__ __forceinline__ void ldsm4t(unsigned r[4], const void* p) {
    unsigned a = (unsigned)__cvta_generic_to_shared(p);
    asm volatile("ldmatrix.sync.aligned.m8n8.x4.trans.shared.b16 {%0,%1,%2,%3}, [%4];"
                 : "=r"(r[0]), "=r"(r[1]), "=r"(r[2]), "=r"(r[3]) : "r"(a));
}
__device__ __forceinline__ void mma16816(float c[4], const unsigned a[4],
                                         unsigned b0, unsigned b1) {
    asm volatile(
        "mma.sync.aligned.m16n8k16.row.col.f32.bf16.bf16.f32 "
        "{%0,%1,%2,%3}, {%4,%5,%6,%7}, {%8,%9}, {%0,%1,%2,%3};"
        : "+f"(c[0]), "+f"(c[1]), "+f"(c[2]), "+f"(c[3])
        : "r"(a[0]), "r"(a[1]), "r"(a[2]), "r"(a[3]), "r"(b0), "r"(b1));
}
__device__ __forceinline__ void split_bf16(float v, __nv_bfloat16& h, __nv_bfloat16& l) {
    h = __float2bfloat16(v);
    l = __float2bfloat16(v - __bfloat162float(h));
}

// ---------------- K2: xh = x @ W  -- double-buffered bf16 split MMA --------
// Block 128x64, BK=32, 8 warps (4x2), warp tile 32x32.
// acc = Ah*Bh + Ah*Bl + Al*Bh
#define GBM 128
#define GBN 64
#define GBK 32
// dynamic smem element offsets (bf16 elements)
#define SAH_OFF 0              // [2][128][40]
#define SAL_OFF 10240
#define SBH_OFF 20480          // [2][32][72]
#define SBL_OFF 25088
#define SMEM_ELEMS 29696       // * 2B = 59392 bytes

__global__ __launch_bounds__(256, 2) void k_gemm(const float* __restrict__ A,
                                                 const float* __restrict__ B,
                                                 int Nn) {
    extern __shared__ __nv_bfloat16 sm[];

    int tid  = threadIdx.x;
    int lane = tid & 31;
    int warp = tid >> 5;
    int wm = warp & 3, wn = warp >> 2;
    int brow = blockIdx.x * GBM;
    int bcol = blockIdx.y * GBN;

    float acc[2][4][4];
#pragma unroll
    for (int i = 0; i < 2; i++)
#pragma unroll
        for (int j = 0; j < 4; j++)
#pragma unroll
            for (int k = 0; k < 4; k++) acc[i][j][k] = 0.f;

    // loader coordinates
    int ar  = tid >> 1;            // 0..127 (A row)
    int ac  = (tid & 1) * 16;      // col half
    int agr = brow + ar;
    int brr = tid >> 3;            // 0..31  (B row)
    int bcc = (tid & 7) * 8;       // col base

    float4 a4[4], b4[2];

    // prologue: load k0 = 0
#pragma unroll
    for (int q = 0; q < 4; q++) {
        a4[q] = make_float4(0.f, 0.f, 0.f, 0.f);
        if (agr < Nn) a4[q] = *(const float4*)&A[(size_t)agr * INC + ac + q * 4];
    }
#pragma unroll
    for (int q = 0; q < 2; q++)
        b4[q] = *(const float4*)&B[(size_t)brr * HC + bcol + bcc + q * 4];

    // store tile into buffer p (helper as lambda-like macro)
#define STORE_TILE(p)                                                          \
    do {                                                                       \
        __nv_bfloat16* pAh = sm + SAH_OFF + (p) * 5120 + ar * 40 + ac;         \
        __nv_bfloat16* pAl = sm + SAL_OFF + (p) * 5120 + ar * 40 + ac;         \
        _Pragma("unroll")                                                      \
        for (int q = 0; q < 4; q++) {                                          \
            float vs[4] = {a4[q].x, a4[q].y, a4[q].z, a4[q].w};                \
            _Pragma("unroll")                                                  \
            for (int u = 0; u < 4; u += 2) {                                   \
                __nv_bfloat16 h0, l0, h1, l1;                                  \
                split_bf16(vs[u], h0, l0);                                     \
                split_bf16(vs[u + 1], h1, l1);                                 \
                *(__nv_bfloat162*)(pAh + q * 4 + u) = __nv_bfloat162(h0, h1);  \
                *(__nv_bfloat162*)(pAl + q * 4 + u) = __nv_bfloat162(l0, l1);  \
            }                                                                  \
        }                                                                      \
        __nv_bfloat16* pBh = sm + SBH_OFF + (p) * 2304 + brr * 72 + bcc;       \
        __nv_bfloat16* pBl = sm + SBL_OFF + (p) * 2304 + brr * 72 + bcc;       \
        _Pragma("unroll")                                                      \
        for (int q = 0; q < 2; q++) {                                          \
            float vs[4] = {b4[q].x, b4[q].y, b4[q].z, b4[q].w};                \
            _Pragma("unroll")                                                  \
            for (int u = 0; u < 4; u += 2) {                                   \
                __nv_bfloat16 h0, l0, h1, l1;                                  \
                split_bf16(vs[u], h0, l0);                                     \
                split_bf16(vs[u + 1], h1, l1);                                 \
                *(__nv_bfloat162*)(pBh + q * 4 + u) = __nv_bfloat162(h0, h1);  \
                *(__nv_bfloat162*)(pBl + q * 4 + u) = __nv_bfloat162(l0, l1);  \
            }                                                                  \
        }                                                                      \
    } while (0)

    STORE_TILE(0);
    __syncthreads();

#pragma unroll
    for (int it = 0; it < INC / GBK; it++) {
        int p = it & 1;
        // prefetch next K tile into registers (latency hidden by compute)
        if (it < INC / GBK - 1) {
            int k0 = (it + 1) * GBK;
#pragma unroll
            for (int q = 0; q < 4; q++) {
                a4[q] = make_float4(0.f, 0.f, 0.f, 0.f);
                if (agr < Nn)
                    a4[q] = *(const float4*)&A[(size_t)agr * INC + k0 + ac + q * 4];
            }
#pragma unroll
            for (int q = 0; q < 2; q++)
                b4[q] = *(const float4*)&B[(size_t)(k0 + brr) * HC + bcol + bcc + q * 4];
        }

        // compute on buffer p
        const __nv_bfloat16* bAh = sm + SAH_OFF + p * 5120;
        const __nv_bfloat16* bAl = sm + SAL_OFF + p * 5120;
        const __nv_bfloat16* bBh = sm + SBH_OFF + p * 2304;
        const __nv_bfloat16* bBl = sm + SBL_OFF + p * 2304;
#pragma unroll
        for (int ks = 0; ks < 2; ks++) {
            unsigned Ah[2][4], Al[2][4], Bh[2][4], Bl[2][4];
            int akk = ks * 16 + (lane >> 4) * 8;
#pragma unroll
            for (int mt = 0; mt < 2; mt++) {
                int r = wm * 32 + mt * 16 + (lane & 15);
                ldsm4(Ah[mt], bAh + r * 40 + akk);
                ldsm4(Al[mt], bAl + r * 40 + akk);
            }
            int bkr = ks * 16 + ((lane >> 3) & 1) * 8 + (lane & 7);
#pragma unroll
            for (int pp = 0; pp < 2; pp++) {
                int bnc = wn * 32 + pp * 16 + (lane >> 4) * 8;
                ldsm4t(Bh[pp], bBh + bkr * 72 + bnc);
                ldsm4t(Bl[pp], bBl + bkr * 72 + bnc);
            }
#pragma unroll
            for (int mt = 0; mt < 2; mt++)
#pragma unroll
                for (int nt = 0; nt < 4; nt++) {
                    int pp = nt >> 1, i0 = (nt & 1) * 2;
                    mma16816(acc[mt][nt], Ah[mt], Bh[pp][i0], Bh[pp][i0 + 1]);
                    mma16816(acc[mt][nt], Ah[mt], Bl[pp][i0], Bl[pp][i0 + 1]);
                    mma16816(acc[mt][nt], Al[mt], Bh[pp][i0], Bh[pp][i0 + 1]);
                }
        }

        // store prefetched tile into the other buffer
        if (it < INC / GBK - 1) {
            STORE_TILE(p ^ 1);
            __syncthreads();
        }
    }

    // epilogue
#pragma unroll
    for (int mt = 0; mt < 2; mt++) {
        int r0 = brow + wm * 32 + mt * 16 + (lane >> 2);
#pragma unroll
        for (int nt = 0; nt < 4; nt++) {
            int c = bcol + wn * 32 + nt * 8 + (lane & 3) * 2;
            if (r0 < Nn)
                *(float2*)&g_xh[(size_t)r0 * HC + c] =
                    make_float2(acc[mt][nt][0], acc[mt][nt][1]);
            if (r0 + 8 < Nn)
                *(float2*)&g_xh[(size_t)(r0 + 8) * HC + c] =
                    make_float2(acc[mt][nt][2], acc[mt][nt][3]);
        }
    }
}

// ---------------- K3: per-node attention logits (warp per node) ------------
__global__ void k_logits(const float* __restrict__ att_src,
                         const float* __restrict__ att_dst, int Nn) {
    int w    = (blockIdx.x * blockDim.x + threadIdx.x) >> 5;
    int lane = threadIdx.x & 31;
    if (w >= Nn) return;
    int cb = lane * 8;
    float4 v0 = *(const float4*)&g_xh[(size_t)w * HC + cb];
    float4 v1 = *(const float4*)&g_xh[(size_t)w * HC + cb + 4];
    float4 s0 = *(const float4*)&att_src[cb];
    float4 s1 = *(const float4*)&att_src[cb + 4];
    float4 d0 = *(const float4*)&att_dst[cb];
    float4 d1 = *(const float4*)&att_dst[cb + 4];
    float s = v0.x * s0.x + v0.y * s0.y + v0.z * s0.z + v0.w * s0.w
            + v1.x * s1.x + v1.y * s1.y + v1.z * s1.z + v1.w * s1.w;
    float d = v0.x * d0.x + v0.y * d0.y + v0.z * d0.z + v0.w * d0.w
            + v1.x * d1.x + v1.y * d1.y + v1.z * d1.z + v1.w * d1.w;
    s += __shfl_xor_sync(0xFFFFFFFFu, s, 1);
    s += __shfl_xor_sync(0xFFFFFFFFu, s, 2);
    d += __shfl_xor_sync(0xFFFFFFFFu, d, 1);
    d += __shfl_xor_sync(0xFFFFFFFFu, d, 2);
    if ((lane & 3) == 0) {
        g_asrc[w * NHEAD + (lane >> 2)] = s;
        g_adst[w * NHEAD + (lane >> 2)] = d;
    }
}

// ---------------- K4: exclusive scan -> CSR offsets (warp-shuffle) ---------
__global__ void k_scan(int Nn) {
    __shared__ int wsum[32];
    __shared__ int carry;
    int tid = threadIdx.x, lane = tid & 31, wid = tid >> 5;
    if (tid == 0) { carry = 0; g_off[0] = 0; }
    __syncthreads();
    for (int base = 0; base < Nn; base += 1024) {
        int i = base + tid;
        int v = (i < Nn) ? g_cnt[i] : 0;
        int sv = v;
#pragma unroll
        for (int o = 1; o < 32; o <<= 1) {
            int t = __shfl_up_sync(0xFFFFFFFFu, sv, o);
            if (lane >= o) sv += t;
        }
        if (lane == 31) wsum[wid] = sv;
        __syncthreads();
        if (wid == 0) {
            int ws = wsum[lane];
#pragma unroll
            for (int o = 1; o < 32; o <<= 1) {
                int t = __shfl_up_sync(0xFFFFFFFFu, ws, o);
                if (lane >= o) ws += t;
            }
            wsum[lane] = ws;
        }
        __syncthreads();
        int add = carry + (wid > 0 ? wsum[wid - 1] : 0);
        if (i < Nn) g_off[i + 1] = sv + add;
        __syncthreads();
        if (tid == 0) carry += wsum[31];
        __syncthreads();
    }
}

// ---------------- K5: scatter edges into dst-sorted order ------------------
__global__ void k_scatter(int E) {
    int e = blockIdx.x * blockDim.x + threadIdx.x;
    if (e >= E) return;
    int s = g_edges[e];
    int d = g_edges[E + e];
    int pos = g_off[d] + atomicAdd(&g_fill[d], 1);
    g_ssrc[pos] = s;
}

// ---------------- K6: warp-per-node softmax + aggregation (no atomics) -----
__global__ __launch_bounds__(256) void k_agg(const float* __restrict__ x,
                                             const float* __restrict__ bias,
                                             float* __restrict__ out, int Nn) {
    int d    = (blockIdx.x * blockDim.x + threadIdx.x) >> 5;
    int lane = threadIdx.x & 31;
    if (d >= Nn) return;
    int h  = lane >> 2;        // head for this lane's 8 channels
    int cb = lane * 8;         // channel base

    float adst_h = __ldg(&g_adst[d * NHEAD + h]);

    // self loop contribution
    float e0 = __ldg(&g_asrc[d * NHEAD + h]) + adst_h;
    e0 = (e0 > 0.f) ? e0 : 0.2f * e0;
    float ex = __expf(e0);
    float dn = ex;
    float4 v0 = __ldg((const float4*)&g_xh[(size_t)d * HC + cb]);
    float4 v1 = __ldg((const float4*)&g_xh[(size_t)d * HC + cb + 4]);
    float a0 = ex * v0.x, a1 = ex * v0.y, a2 = ex * v0.z, a3 = ex * v0.w;
    float a4 = ex * v1.x, a5 = ex * v1.y, a6 = ex * v1.z, a7 = ex * v1.w;

    int beg = g_off[d], end = g_off[d + 1];
    int j = beg;
    // 2-edge unrolled main loop: all loads issued before use (MLP ~6)
    for (; j + 1 < end; j += 2) {
        int s0 = __ldg(&g_ssrc[j]);
        int s1 = __ldg(&g_ssrc[j + 1]);
        float ea = __ldg(&g_asrc[s0 * NHEAD + h]) + adst_h;
        float eb = __ldg(&g_asrc[s1 * NHEAD + h]) + adst_h;
        float4 u00 = __ldg((const float4*)&g_xh[(size_t)s0 * HC + cb]);
        float4 u01 = __ldg((const float4*)&g_xh[(size_t)s0 * HC + cb + 4]);
        float4 u10 = __ldg((const float4*)&g_xh[(size_t)s1 * HC + cb]);
        float4 u11 = __ldg((const float4*)&g_xh[(size_t)s1 * HC + cb + 4]);
        ea = (ea > 0.f) ? ea : 0.2f * ea;
        eb = (eb > 0.f) ? eb : 0.2f * eb;
        float wa = __expf(ea);
        float wb = __expf(eb);
        dn += wa + wb;
        a0 += wa * u00.x + wb * u10.x; a1 += wa * u00.y + wb * u10.y;
        a2 += wa * u00.z + wb * u10.z; a3 += wa * u00.w + wb * u10.w;
        a4 += wa * u01.x + wb * u11.x; a5 += wa * u01.y + wb * u11.y;
        a6 += wa * u01.z + wb * u11.z; a7 += wa * u01.w + wb * u11.w;
    }
    if (j < end) {
        int s = __ldg(&g_ssrc[j]);
        float e = __ldg(&g_asrc[s * NHEAD + h]) + adst_h;
        e = (e > 0.f) ? e : 0.2f * e;
        float w = __expf(e);
        dn += w;
        float4 u0 = __ldg((const float4*)&g_xh[(size_t)s * HC + cb]);
        float4 u1 = __ldg((const float4*)&g_xh[(size_t)s * HC + cb + 4]);
        a0 += w * u0.x; a1 += w * u0.y; a2 += w * u0.z; a3 += w * u0.w;
        a4 += w * u1.x; a5 += w * u1.y; a6 += w * u1.z; a7 += w * u1.w;
    }

    float inv = 1.f / (dn + 1e-16f);
    float4 xb0 = __ldg((const float4*)&x[(size_t)d * HC + cb]);
    float4 xb1 = __ldg((const float4*)&x[(size_t)d * HC + cb + 4]);
    float4 b0  = __ldg((const float4*)&bias[cb]);
    float4 b1  = __ldg((const float4*)&bias[cb + 4]);
    float4 o0 = make_float4(a0 * inv + xb0.x + b0.x, a1 * inv + xb0.y + b0.y,
                            a2 * inv + xb0.z + b0.z, a3 * inv + xb0.w + b0.w);
    float4 o1 = make_float4(a4 * inv + xb1.x + b1.x, a5 * inv + xb1.y + b1.y,
                            a6 * inv + xb1.z + b1.z, a7 * inv + xb1.w + b1.w);
    *(float4*)&out[(size_t)d * HC + cb]     = o0;
    *(float4*)&out[(size_t)d * HC + cb + 4] = o1;
    if ((lane & 3) == 0) g_denom[d * NHEAD + h] = dn;
}

// ---------------- K7: per-edge alpha output ---------------------------------
__global__ void k_alpha(float* __restrict__ alpha_out, int Etot, int E) {
    int e = blockIdx.x * blockDim.x + threadIdx.x;
    if (e >= Etot) return;
    int s, d;
    if (e < E) { s = g_edges[e]; d = g_edges[E + e]; }
    else       { s = d = e - E; }
    float4 s0 = __ldg((const float4*)&g_asrc[(size_t)s * NHEAD]);
    float4 s1 = __ldg((const float4*)&g_asrc[(size_t)s * NHEAD + 4]);
    float4 d0 = __ldg((const float4*)&g_adst[(size_t)d * NHEAD]);
    float4 d1 = __ldg((const float4*)&g_adst[(size_t)d * NHEAD + 4]);
    float4 n0 = __ldg((const float4*)&g_denom[(size_t)d * NHEAD]);
    float4 n1 = __ldg((const float4*)&g_denom[(size_t)d * NHEAD + 4]);
    float ev[8] = { s0.x + d0.x, s0.y + d0.y, s0.z + d0.z, s0.w + d0.w,
                    s1.x + d1.x, s1.y + d1.y, s1.z + d1.z, s1.w + d1.w };
    float dns[8] = { n0.x, n0.y, n0.z, n0.w, n1.x, n1.y, n1.z, n1.w };
    float al[8];
#pragma unroll
    for (int h = 0; h < NHEAD; h++) {
        float v = ev[h];
        v = (v > 0.f) ? v : 0.2f * v;
        al[h] = __expf(v) / (dns[h] + 1e-16f);
    }
    *(float4*)&alpha_out[(size_t)e * NHEAD]     = make_float4(al[0], al[1], al[2], al[3]);
    *(float4*)&alpha_out[(size_t)e * NHEAD + 4] = make_float4(al[4], al[5], al[6], al[7]);
}

// ---------------- host launcher ---------------------------------------------
extern "C" void kernel_launch(void* const* d_in, const int* in_sizes, int n_in,
                              void* d_out, int out_size) {
    const float* x       = (const float*)d_in[0];
    const void*  ei      = d_in[1];
    const float* W       = (const float*)d_in[2];
    const float* att_src = (const float*)d_in[3];
    const float* att_dst = (const float*)d_in[4];
    const float* bias    = (const float*)d_in[5];

    int Nn   = in_sizes[0] / INC;
    int E    = in_sizes[1] / 2;
    int Etot = E + Nn;

    float* out = (float*)d_out;
    float* alpha_out = nullptr;
    if ((long long)out_size >= (long long)Nn * HC + (long long)Etot * NHEAD)
        alpha_out = out + (size_t)Nn * HC;

    // edge index conversion + CSR build
    k_detect<<<1, 256>>>((const int*)ei, 16384);
    k_zero<<<(Nn + 255) / 256, 256>>>(Nn);
    k_convert<<<(2 * E + 255) / 256, 256>>>(ei, 2 * E, E);

    // projection GEMM (independent of edges)
    static int smem_set = 0;
    if (!smem_set) {
        cudaFuncSetAttribute(k_gemm, cudaFuncAttributeMaxDynamicSharedMemorySize,
                             SMEM_ELEMS * 2);
        smem_set = 1;
    }
    dim3 ggrid((Nn + GBM - 1) / GBM, HC / GBN);
    k_gemm<<<ggrid, 256, SMEM_ELEMS * 2>>>(x, W, Nn);
    k_logits<<<(Nn * 32 + 255) / 256, 256>>>(att_src, att_dst, Nn);

    // CSR offsets + dst-sorted edge list
    k_scan<<<1, 1024>>>(Nn);
    k_scatter<<<(E + 255) / 256, 256>>>(E);

    // fused softmax + aggregation + residual + bias (no atomics)
    k_agg<<<(Nn * 32 + 255) / 256, 256>>>(x, bias, out, Nn);

    // alpha output
    if (alpha_out)
        k_alpha<<<(Etot + 255) / 256, 256>>>(alpha_out, Etot, E);
}

// round 6
// speedup vs baseline: 2.3281x; 1.1026x over previous
#include <cuda_runtime.h>
#include <cuda_bf16.h>

// Problem constants (fixed shapes from the reference)
#define NMAX 50000
#define EMAX 800000
#define INC  256
#define NHEAD 8
#define CH   32
#define HC   256   // NHEAD*CH

// ---------------- scratch (static device globals; no allocs allowed) -------
__device__ float    g_xh[NMAX * HC];            // projected features (N,H,C)
__device__ float    g_asrc[NMAX * NHEAD];       // per-node src logits
__device__ float    g_adst[NMAX * NHEAD];       // per-node dst logits
__device__ float    g_denom[NMAX * NHEAD];      // softmax denominators
__device__ int      g_edges[2 * EMAX];          // converted int32 edge index
__device__ int      g_cnt[NMAX];                // in-degree histogram
__device__ int      g_fill[NMAX];               // scatter fill counters
__device__ int      g_off[NMAX + 1];            // CSR offsets
__device__ int      g_ssrc[EMAX];               // src node per dst-sorted edge
__device__ int      g_is64;

// ---------------- K0: detect int64 vs int32 edge_index ---------------------
__global__ void k_detect(const int* __restrict__ p, int n_words) {
    __shared__ int s;
    if (threadIdx.x == 0) s = 0;
    __syncthreads();
    int acc = 0;
    for (int i = 1 + 2 * (int)threadIdx.x; i < n_words; i += 2 * blockDim.x)
        acc |= p[i];
    if (acc) atomicOr(&s, 1);
    __syncthreads();
    if (threadIdx.x == 0) g_is64 = (s == 0) ? 1 : 0;
}

// ---------------- K0b: zero histogram + fill counters ----------------------
__global__ void k_zero(int Nn) {
    int i = blockIdx.x * blockDim.x + threadIdx.x;
    if (i < Nn) { g_cnt[i] = 0; g_fill[i] = 0; }
}

// ---------------- K1: convert edge index to int32 + dst histogram ----------
__global__ void k_convert(const void* __restrict__ p, int twoE, int E) {
    int i = blockIdx.x * blockDim.x + threadIdx.x;
    if (i >= twoE) return;
    int v;
    if (g_is64) v = (int)((const long long*)p)[i];
    else        v = ((const int*)p)[i];
    g_edges[i] = v;
    if (i >= E) atomicAdd(&g_cnt[v], 1);   // dst half -> in-degree histogram
}

// ---------------- MMA helpers ----------------------------------------------
__device__ __forceinline__ void ldsm4(unsigned r[4], const void* p) {
    unsigned a = (unsigned)__cvta_generic_to_shared(p);
    asm volatile("ldmatrix.sync.aligned.m8n8.x4.shared.b16 {%0,%1,%2,%3}, [%4];"
                 : "=r"(r[0]), "=r"(r[1]), "=r"(r[2]), "=r"(r[3]) : "r"(a));
}
__device__ __forceinline__ void ldsm4t(unsigned r[4], const void* p) {
    unsigned a = (unsigned)__cvta_generic_to_shared(p);
    asm volatile("ldmatrix.sync.aligned.m8n8.x4.trans.shared.b16 {%0,%1,%2,%3}, [%4];"
                 : "=r"(r[0]), "=r"(r[1]), "=r"(r[2]), "=r"(r[3]) : "r"(a));
}
__device__ __forceinline__ void mma16816(float c[4], const unsigned a[4],
                                         unsigned b0, unsigned b1) {
    asm volatile(
        "mma.sync.aligned.m16n8k16.row.col.f32.bf16.bf16.f32 "
        "{%0,%1,%2,%3}, {%4,%5,%6,%7}, {%8,%9}, {%0,%1,%2,%3};"
        : "+f"(c[0]), "+f"(c[1]), "+f"(c[2]), "+f"(c[3])
        : "r"(a[0]), "r"(a[1]), "r"(a[2]), "r"(a[3]), "r"(b0), "r"(b1));
}
__device__ __forceinline__ void split_bf16(float v, __nv_bfloat16& h, __nv_bfloat16& l) {
    h = __float2bfloat16(v);
    l = __float2bfloat16(v - __bfloat162float(h));
}

// ---------------- K2: xh = x @ W  -- double-buffered bf16 split MMA --------
// Block 128x64, BK=32, 8 warps (4x2), warp tile 32x32.
// acc = Ah*Bh + Ah*Bl + Al*Bh
#define GBM 128
#define GBN 64
#define GBK 32
// dynamic smem element offsets (bf16 elements)
#define SAH_OFF 0              // [2][128][40]
#define SAL_OFF 10240
#define SBH_OFF 20480          // [2][32][72]
#define SBL_OFF 25088
#define SMEM_ELEMS 29696       // * 2B = 59392 bytes

__global__ __launch_bounds__(256, 2) void k_gemm(const float* __restrict__ A,
                                                 const float* __restrict__ B,
                                                 int Nn) {
    extern __shared__ __nv_bfloat16 sm[];

    int tid  = threadIdx.x;
    int lane = tid & 31;
    int warp = tid >> 5;
    int wm = warp & 3, wn = warp >> 2;
    int brow = blockIdx.x * GBM;
    int bcol = blockIdx.y * GBN;

    float acc[2][4][4];
#pragma unroll
    for (int i = 0; i < 2; i++)
#pragma unroll
        for (int j = 0; j < 4; j++)
#pragma unroll
            for (int k = 0; k < 4; k++) acc[i][j][k] = 0.f;

    // loader coordinates
    int ar  = tid >> 1;            // 0..127 (A row)
    int ac  = (tid & 1) * 16;      // col half
    int agr = brow + ar;
    int brr = tid >> 3;            // 0..31  (B row)
    int bcc = (tid & 7) * 8;       // col base

    float4 a4[4], b4[2];

    // prologue: load k0 = 0
#pragma unroll
    for (int q = 0; q < 4; q++) {
        a4[q] = make_float4(0.f, 0.f, 0.f, 0.f);
        if (agr < Nn) a4[q] = *(const float4*)&A[(size_t)agr * INC + ac + q * 4];
    }
#pragma unroll
    for (int q = 0; q < 2; q++)
        b4[q] = *(const float4*)&B[(size_t)brr * HC + bcol + bcc + q * 4];

#define STORE_TILE(p)                                                          \
    do {                                                                       \
        __nv_bfloat16* pAh = sm + SAH_OFF + (p) * 5120 + ar * 40 + ac;         \
        __nv_bfloat16* pAl = sm + SAL_OFF + (p) * 5120 + ar * 40 + ac;         \
        _Pragma("unroll")                                                      \
        for (int q = 0; q < 4; q++) {                                          \
            float vs[4] = {a4[q].x, a4[q].y, a4[q].z, a4[q].w};                \
            _Pragma("unroll")                                                  \
            for (int u = 0; u < 4; u += 2) {                                   \
                __nv_bfloat16 h0, l0, h1, l1;                                  \
                split_bf16(vs[u], h0, l0);                                     \
                split_bf16(vs[u + 1], h1, l1);                                 \
                *(__nv_bfloat162*)(pAh + q * 4 + u) = __nv_bfloat162(h0, h1);  \
                *(__nv_bfloat162*)(pAl + q * 4 + u) = __nv_bfloat162(l0, l1);  \
            }                                                                  \
        }                                                                      \
        __nv_bfloat16* pBh = sm + SBH_OFF + (p) * 2304 + brr * 72 + bcc;       \
        __nv_bfloat16* pBl = sm + SBL_OFF + (p) * 2304 + brr * 72 + bcc;       \
        _Pragma("unroll")                                                      \
        for (int q = 0; q < 2; q++) {                                          \
            float vs[4] = {b4[q].x, b4[q].y, b4[q].z, b4[q].w};                \
            _Pragma("unroll")                                                  \
            for (int u = 0; u < 4; u += 2) {                                   \
                __nv_bfloat16 h0, l0, h1, l1;                                  \
                split_bf16(vs[u], h0, l0);                                     \
                split_bf16(vs[u + 1], h1, l1);                                 \
                *(__nv_bfloat162*)(pBh + q * 4 + u) = __nv_bfloat162(h0, h1);  \
                *(__nv_bfloat162*)(pBl + q * 4 + u) = __nv_bfloat162(l0, l1);  \
            }                                                                  \
        }                                                                      \
    } while (0)

    STORE_TILE(0);
    __syncthreads();

#pragma unroll
    for (int it = 0; it < INC / GBK; it++) {
        int p = it & 1;
        // prefetch next K tile into registers (latency hidden by compute)
        if (it < INC / GBK - 1) {
            int k0 = (it + 1) * GBK;
#pragma unroll
            for (int q = 0; q < 4; q++) {
                a4[q] = make_float4(0.f, 0.f, 0.f, 0.f);
                if (agr < Nn)
                    a4[q] = *(const float4*)&A[(size_t)agr * INC + k0 + ac + q * 4];
            }
#pragma unroll
            for (int q = 0; q < 2; q++)
                b4[q] = *(const float4*)&B[(size_t)(k0 + brr) * HC + bcol + bcc + q * 4];
        }

        // compute on buffer p
        const __nv_bfloat16* bAh = sm + SAH_OFF + p * 5120;
        const __nv_bfloat16* bAl = sm + SAL_OFF + p * 5120;
        const __nv_bfloat16* bBh = sm + SBH_OFF + p * 2304;
        const __nv_bfloat16* bBl = sm + SBL_OFF + p * 2304;
#pragma unroll
        for (int ks = 0; ks < 2; ks++) {
            unsigned Ah[2][4], Al[2][4], Bh[2][4], Bl[2][4];
            int akk = ks * 16 + (lane >> 4) * 8;
#pragma unroll
            for (int mt = 0; mt < 2; mt++) {
                int r = wm * 32 + mt * 16 + (lane & 15);
                ldsm4(Ah[mt], bAh + r * 40 + akk);
                ldsm4(Al[mt], bAl + r * 40 + akk);
            }
            int bkr = ks * 16 + ((lane >> 3) & 1) * 8 + (lane & 7);
#pragma unroll
            for (int pp = 0; pp < 2; pp++) {
                int bnc = wn * 32 + pp * 16 + (lane >> 4) * 8;
                ldsm4t(Bh[pp], bBh + bkr * 72 + bnc);
                ldsm4t(Bl[pp], bBl + bkr * 72 + bnc);
            }
#pragma unroll
            for (int mt = 0; mt < 2; mt++)
#pragma unroll
                for (int nt = 0; nt < 4; nt++) {
                    int pp = nt >> 1, i0 = (nt & 1) * 2;
                    mma16816(acc[mt][nt], Ah[mt], Bh[pp][i0], Bh[pp][i0 + 1]);
                    mma16816(acc[mt][nt], Ah[mt], Bl[pp][i0], Bl[pp][i0 + 1]);
                    mma16816(acc[mt][nt], Al[mt], Bh[pp][i0], Bh[pp][i0 + 1]);
                }
        }

        // store prefetched tile into the other buffer
        if (it < INC / GBK - 1) {
            STORE_TILE(p ^ 1);
            __syncthreads();
        }
    }

    // epilogue
#pragma unroll
    for (int mt = 0; mt < 2; mt++) {
        int r0 = brow + wm * 32 + mt * 16 + (lane >> 2);
#pragma unroll
        for (int nt = 0; nt < 4; nt++) {
            int c = bcol + wn * 32 + nt * 8 + (lane & 3) * 2;
            if (r0 < Nn)
                *(float2*)&g_xh[(size_t)r0 * HC + c] =
                    make_float2(acc[mt][nt][0], acc[mt][nt][1]);
            if (r0 + 8 < Nn)
                *(float2*)&g_xh[(size_t)(r0 + 8) * HC + c] =
                    make_float2(acc[mt][nt][2], acc[mt][nt][3]);
        }
    }
}

// ---------------- K3: per-node attention logits (warp per node) ------------
__global__ void k_logits(const float* __restrict__ att_src,
                         const float* __restrict__ att_dst, int Nn) {
    int w    = (blockIdx.x * blockDim.x + threadIdx.x) >> 5;
    int lane = threadIdx.x & 31;
    if (w >= Nn) return;
    int cb = lane * 8;
    float4 v0 = *(const float4*)&g_xh[(size_t)w * HC + cb];
    float4 v1 = *(const float4*)&g_xh[(size_t)w * HC + cb + 4];
    float4 s0 = *(const float4*)&att_src[cb];
    float4 s1 = *(const float4*)&att_src[cb + 4];
    float4 d0 = *(const float4*)&att_dst[cb];
    float4 d1 = *(const float4*)&att_dst[cb + 4];
    float s = v0.x * s0.x + v0.y * s0.y + v0.z * s0.z + v0.w * s0.w
            + v1.x * s1.x + v1.y * s1.y + v1.z * s1.z + v1.w * s1.w;
    float d = v0.x * d0.x + v0.y * d0.y + v0.z * d0.z + v0.w * d0.w
            + v1.x * d1.x + v1.y * d1.y + v1.z * d1.z + v1.w * d1.w;
    s += __shfl_xor_sync(0xFFFFFFFFu, s, 1);
    s += __shfl_xor_sync(0xFFFFFFFFu, s, 2);
    d += __shfl_xor_sync(0xFFFFFFFFu, d, 1);
    d += __shfl_xor_sync(0xFFFFFFFFu, d, 2);
    if ((lane & 3) == 0) {
        g_asrc[w * NHEAD + (lane >> 2)] = s;
        g_adst[w * NHEAD + (lane >> 2)] = d;
    }
}

// ---------------- K4: exclusive scan -> CSR offsets (warp-shuffle) ---------
__global__ void k_scan(int Nn) {
    __shared__ int wsum[32];
    __shared__ int carry;
    int tid = threadIdx.x, lane = tid & 31, wid = tid >> 5;
    if (tid == 0) { carry = 0; g_off[0] = 0; }
    __syncthreads();
    for (int base = 0; base < Nn; base += 1024) {
        int i = base + tid;
        int v = (i < Nn) ? g_cnt[i] : 0;
        int sv = v;
#pragma unroll
        for (int o = 1; o < 32; o <<= 1) {
            int t = __shfl_up_sync(0xFFFFFFFFu, sv, o);
            if (lane >= o) sv += t;
        }
        if (lane == 31) wsum[wid] = sv;
        __syncthreads();
        if (wid == 0) {
            int ws = wsum[lane];
#pragma unroll
            for (int o = 1; o < 32; o <<= 1) {
                int t = __shfl_up_sync(0xFFFFFFFFu, ws, o);
                if (lane >= o) ws += t;
            }
            wsum[lane] = ws;
        }
        __syncthreads();
        int add = carry + (wid > 0 ? wsum[wid - 1] : 0);
        if (i < Nn) g_off[i + 1] = sv + add;
        __syncthreads();
        if (tid == 0) carry += wsum[31];
        __syncthreads();
    }
}

// ---------------- K5: scatter edges into dst-sorted order ------------------
__global__ void k_scatter(int E) {
    int e = blockIdx.x * blockDim.x + threadIdx.x;
    if (e >= E) return;
    int s = g_edges[e];
    int d = g_edges[E + e];
    int pos = g_off[d] + atomicAdd(&g_fill[d], 1);
    g_ssrc[pos] = s;
}

// ---------------- K6: warp-per-node softmax + aggregation (no atomics) -----
__global__ __launch_bounds__(256) void k_agg(const float* __restrict__ x,
                                             const float* __restrict__ bias,
                                             float* __restrict__ out, int Nn) {
    int d    = (blockIdx.x * blockDim.x + threadIdx.x) >> 5;
    int lane = threadIdx.x & 31;
    if (d >= Nn) return;
    int h  = lane >> 2;        // head for this lane's 8 channels
    int cb = lane * 8;         // channel base

    float adst_h = __ldg(&g_adst[d * NHEAD + h]);

    // self loop contribution
    float e0 = __ldg(&g_asrc[d * NHEAD + h]) + adst_h;
    e0 = (e0 > 0.f) ? e0 : 0.2f * e0;
    float ex = __expf(e0);
    float dn = ex;
    float4 v0 = __ldg((const float4*)&g_xh[(size_t)d * HC + cb]);
    float4 v1 = __ldg((const float4*)&g_xh[(size_t)d * HC + cb + 4]);
    float a0 = ex * v0.x, a1 = ex * v0.y, a2 = ex * v0.z, a3 = ex * v0.w;
    float a4 = ex * v1.x, a5 = ex * v1.y, a6 = ex * v1.z, a7 = ex * v1.w;

    int beg = g_off[d], end = g_off[d + 1];
    int j = beg;
    for (; j + 1 < end; j += 2) {
        int s0 = __ldg(&g_ssrc[j]);
        int s1 = __ldg(&g_ssrc[j + 1]);
        float ea = __ldg(&g_asrc[s0 * NHEAD + h]) + adst_h;
        float eb = __ldg(&g_asrc[s1 * NHEAD + h]) + adst_h;
        float4 u00 = __ldg((const float4*)&g_xh[(size_t)s0 * HC + cb]);
        float4 u01 = __ldg((const float4*)&g_xh[(size_t)s0 * HC + cb + 4]);
        float4 u10 = __ldg((const float4*)&g_xh[(size_t)s1 * HC + cb]);
        float4 u11 = __ldg((const float4*)&g_xh[(size_t)s1 * HC + cb + 4]);
        ea = (ea > 0.f) ? ea : 0.2f * ea;
        eb = (eb > 0.f) ? eb : 0.2f * eb;
        float wa = __expf(ea);
        float wb = __expf(eb);
        dn += wa + wb;
        a0 += wa * u00.x + wb * u10.x; a1 += wa * u00.y + wb * u10.y;
        a2 += wa * u00.z + wb * u10.z; a3 += wa * u00.w + wb * u10.w;
        a4 += wa * u01.x + wb * u11.x; a5 += wa * u01.y + wb * u11.y;
        a6 += wa * u01.z + wb * u11.z; a7 += wa * u01.w + wb * u11.w;
    }
    if (j < end) {
        int s = __ldg(&g_ssrc[j]);
        float e = __ldg(&g_asrc[s * NHEAD + h]) + adst_h;
        e = (e > 0.f) ? e : 0.2f * e;
        float w = __expf(e);
        dn += w;
        float4 u0 = __ldg((const float4*)&g_xh[(size_t)s * HC + cb]);
        float4 u1 = __ldg((const float4*)&g_xh[(size_t)s * HC + cb + 4]);
        a0 += w * u0.x; a1 += w * u0.y; a2 += w * u0.z; a3 += w * u0.w;
        a4 += w * u1.x; a5 += w * u1.y; a6 += w * u1.z; a7 += w * u1.w;
    }

    float inv = 1.f / (dn + 1e-16f);
    float4 xb0 = __ldg((const float4*)&x[(size_t)d * HC + cb]);
    float4 xb1 = __ldg((const float4*)&x[(size_t)d * HC + cb + 4]);
    float4 b0  = __ldg((const float4*)&bias[cb]);
    float4 b1  = __ldg((const float4*)&bias[cb + 4]);
    float4 o0 = make_float4(a0 * inv + xb0.x + b0.x, a1 * inv + xb0.y + b0.y,
                            a2 * inv + xb0.z + b0.z, a3 * inv + xb0.w + b0.w);
    float4 o1 = make_float4(a4 * inv + xb1.x + b1.x, a5 * inv + xb1.y + b1.y,
                            a6 * inv + xb1.z + b1.z, a7 * inv + xb1.w + b1.w);
    *(float4*)&out[(size_t)d * HC + cb]     = o0;
    *(float4*)&out[(size_t)d * HC + cb + 4] = o1;
    if ((lane & 3) == 0) g_denom[d * NHEAD + h] = dn;
}

// ---------------- K7: per-edge alpha output ---------------------------------
__global__ void k_alpha(float* __restrict__ alpha_out, int Etot, int E) {
    int e = blockIdx.x * blockDim.x + threadIdx.x;
    if (e >= Etot) return;
    int s, d;
    if (e < E) { s = g_edges[e]; d = g_edges[E + e]; }
    else       { s = d = e - E; }
    float4 s0 = __ldg((const float4*)&g_asrc[(size_t)s * NHEAD]);
    float4 s1 = __ldg((const float4*)&g_asrc[(size_t)s * NHEAD + 4]);
    float4 d0 = __ldg((const float4*)&g_adst[(size_t)d * NHEAD]);
    float4 d1 = __ldg((const float4*)&g_adst[(size_t)d * NHEAD + 4]);
    float4 n0 = __ldg((const float4*)&g_denom[(size_t)d * NHEAD]);
    float4 n1 = __ldg((const float4*)&g_denom[(size_t)d * NHEAD + 4]);
    float ev[8] = { s0.x + d0.x, s0.y + d0.y, s0.z + d0.z, s0.w + d0.w,
                    s1.x + d1.x, s1.y + d1.y, s1.z + d1.z, s1.w + d1.w };
    float dns[8] = { n0.x, n0.y, n0.z, n0.w, n1.x, n1.y, n1.z, n1.w };
    float al[8];
#pragma unroll
    for (int h = 0; h < NHEAD; h++) {
        float v = ev[h];
        v = (v > 0.f) ? v : 0.2f * v;
        al[h] = __expf(v) / (dns[h] + 1e-16f);
    }
    *(float4*)&alpha_out[(size_t)e * NHEAD]     = make_float4(al[0], al[1], al[2], al[3]);
    *(float4*)&alpha_out[(size_t)e * NHEAD + 4] = make_float4(al[4], al[5], al[6], al[7]);
}

// ---------------- host launcher ---------------------------------------------
extern "C" void kernel_launch(void* const* d_in, const int* in_sizes, int n_in,
                              void* d_out, int out_size) {
    const float* x       = (const float*)d_in[0];
    const void*  ei      = d_in[1];
    const float* W       = (const float*)d_in[2];
    const float* att_src = (const float*)d_in[3];
    const float* att_dst = (const float*)d_in[4];
    const float* bias    = (const float*)d_in[5];

    int Nn   = in_sizes[0] / INC;
    int E    = in_sizes[1] / 2;
    int Etot = E + Nn;

    float* out = (float*)d_out;
    float* alpha_out = nullptr;
    if ((long long)out_size >= (long long)Nn * HC + (long long)Etot * NHEAD)
        alpha_out = out + (size_t)Nn * HC;

    // one-time host objects (no device memory involved)
    static cudaStream_t s1 = nullptr;
    static cudaEvent_t  evFork = nullptr, evJoin = nullptr;
    static int          inited = 0;
    if (!inited) {
        cudaStreamCreateWithFlags(&s1, cudaStreamNonBlocking);
        cudaEventCreateWithFlags(&evFork, cudaEventDisableTiming);
        cudaEventCreateWithFlags(&evJoin, cudaEventDisableTiming);
        cudaFuncSetAttribute(k_gemm, cudaFuncAttributeMaxDynamicSharedMemorySize,
                             SMEM_ELEMS * 2);
        inited = 1;
    }

    // fork: branch stream s1 runs GEMM + logits, main stream builds CSR
    cudaEventRecord(evFork, 0);
    cudaStreamWaitEvent(s1, evFork, 0);

    // --- branch A (s1): projection GEMM + per-node logits ---
    dim3 ggrid((Nn + GBM - 1) / GBM, HC / GBN);
    k_gemm<<<ggrid, 256, SMEM_ELEMS * 2, s1>>>(x, W, Nn);
    k_logits<<<(Nn * 32 + 255) / 256, 256, 0, s1>>>(att_src, att_dst, Nn);

    // --- branch B (main stream): edge conversion + CSR build ---
    k_detect<<<1, 256>>>((const int*)ei, 16384);
    k_zero<<<(Nn + 255) / 256, 256>>>(Nn);
    k_convert<<<(2 * E + 255) / 256, 256>>>(ei, 2 * E, E);
    k_scan<<<1, 1024>>>(Nn);
    k_scatter<<<(E + 255) / 256, 256>>>(E);

    // join: main stream waits for branch A
    cudaEventRecord(evJoin, s1);
    cudaStreamWaitEvent(0, evJoin, 0);

    // fused softmax + aggregation + residual + bias (no atomics)
    k_agg<<<(Nn * 32 + 255) / 256, 256>>>(x, bias, out, Nn);

    // alpha output
    if (alpha_out)
        k_alpha<<<(Etot + 255) / 256, 256>>>(alpha_out, Etot, E);
}

// round 7
// speedup vs baseline: 2.5851x; 1.1104x over previous
#include <cuda_runtime.h>
#include <cuda_bf16.h>
#include <cuda_fp16.h>

// Problem constants (fixed shapes from the reference)
#define NMAX 50000
#define EMAX 800000
#define INC  256
#define NHEAD 8
#define CH   32
#define HC   256   // NHEAD*CH

// ---------------- scratch (static device globals; no allocs allowed) -------
__device__ float    g_xh[NMAX * HC];            // projected features (N,H,C) fp32
__device__ __half   g_xhh[NMAX * HC];           // fp16 copy for gathers
__device__ float    g_asrc[NMAX * NHEAD];       // per-node src logits
__device__ float    g_adst[NMAX * NHEAD];       // per-node dst logits
__device__ int      g_edges[2 * EMAX];          // converted int32 edge index
__device__ int      g_cnt[NMAX];                // in-degree histogram
__device__ int      g_fill[NMAX];               // scatter fill counters
__device__ int      g_off[NMAX + 1];            // CSR offsets
__device__ int2     g_sedge[EMAX];              // (src, orig edge id) dst-sorted
__device__ int      g_is64;

// ---------------- K0: detect int64 vs int32 edge_index ---------------------
__global__ void k_detect(const int* __restrict__ p, int n_words) {
    __shared__ int s;
    if (threadIdx.x == 0) s = 0;
    __syncthreads();
    int acc = 0;
    for (int i = 1 + 2 * (int)threadIdx.x; i < n_words; i += 2 * blockDim.x)
        acc |= p[i];
    if (acc) atomicOr(&s, 1);
    __syncthreads();
    if (threadIdx.x == 0) g_is64 = (s == 0) ? 1 : 0;
}

// ---------------- K0b: zero histogram + fill counters ----------------------
__global__ void k_zero(int Nn) {
    int i = blockIdx.x * blockDim.x + threadIdx.x;
    if (i < Nn) { g_cnt[i] = 0; g_fill[i] = 0; }
}

// ---------------- K1: convert edge index to int32 + dst histogram ----------
__global__ void k_convert(const void* __restrict__ p, int twoE, int E) {
    int i = blockIdx.x * blockDim.x + threadIdx.x;
    if (i >= twoE) return;
    int v;
    if (g_is64) v = (int)((const long long*)p)[i];
    else        v = ((const int*)p)[i];
    g_edges[i] = v;
    if (i >= E) atomicAdd(&g_cnt[v], 1);   // dst half -> in-degree histogram
}

// ---------------- MMA helpers ----------------------------------------------
__device__ __forceinline__ void ldsm4(unsigned r[4], const void* p) {
    unsigned a = (unsigned)__cvta_generic_to_shared(p);
    asm volatile("ldmatrix.sync.aligned.m8n8.x4.shared.b16 {%0,%1,%2,%3}, [%4];"
                 : "=r"(r[0]), "=r"(r[1]), "=r"(r[2]), "=r"(r[3]) : "r"(a));
}
__device__ __forceinline__ void ldsm4t(unsigned r[4], const void* p) {
    unsigned a = (unsigned)__cvta_generic_to_shared(p);
    asm volatile("ldmatrix.sync.aligned.m8n8.x4.trans.shared.b16 {%0,%1,%2,%3}, [%4];"
                 : "=r"(r[0]), "=r"(r[1]), "=r"(r[2]), "=r"(r[3]) : "r"(a));
}
__device__ __forceinline__ void mma16816(float c[4], const unsigned a[4],
                                         unsigned b0, unsigned b1) {
    asm volatile(
        "mma.sync.aligned.m16n8k16.row.col.f32.bf16.bf16.f32 "
        "{%0,%1,%2,%3}, {%4,%5,%6,%7}, {%8,%9}, {%0,%1,%2,%3};"
        : "+f"(c[0]), "+f"(c[1]), "+f"(c[2]), "+f"(c[3])
        : "r"(a[0]), "r"(a[1]), "r"(a[2]), "r"(a[3]), "r"(b0), "r"(b1));
}
__device__ __forceinline__ void split_bf16(float v, __nv_bfloat16& h, __nv_bfloat16& l) {
    h = __float2bfloat16(v);
    l = __float2bfloat16(v - __bfloat162float(h));
}

// ---------------- K2: xh = x @ W  -- double-buffered bf16 split MMA --------
#define GBM 128
#define GBN 64
#define GBK 32
#define SAH_OFF 0              // [2][128][40]
#define SAL_OFF 10240
#define SBH_OFF 20480          // [2][32][72]
#define SBL_OFF 25088
#define SMEM_ELEMS 29696       // * 2B = 59392 bytes

__global__ __launch_bounds__(256, 2) void k_gemm(const float* __restrict__ A,
                                                 const float* __restrict__ B,
                                                 int Nn) {
    extern __shared__ __nv_bfloat16 sm[];

    int tid  = threadIdx.x;
    int lane = tid & 31;
    int warp = tid >> 5;
    int wm = warp & 3, wn = warp >> 2;
    int brow = blockIdx.x * GBM;
    int bcol = blockIdx.y * GBN;

    float acc[2][4][4];
#pragma unroll
    for (int i = 0; i < 2; i++)
#pragma unroll
        for (int j = 0; j < 4; j++)
#pragma unroll
            for (int k = 0; k < 4; k++) acc[i][j][k] = 0.f;

    int ar  = tid >> 1;
    int ac  = (tid & 1) * 16;
    int agr = brow + ar;
    int brr = tid >> 3;
    int bcc = (tid & 7) * 8;

    float4 a4[4], b4[2];

#pragma unroll
    for (int q = 0; q < 4; q++) {
        a4[q] = make_float4(0.f, 0.f, 0.f, 0.f);
        if (agr < Nn) a4[q] = *(const float4*)&A[(size_t)agr * INC + ac + q * 4];
    }
#pragma unroll
    for (int q = 0; q < 2; q++)
        b4[q] = *(const float4*)&B[(size_t)brr * HC + bcol + bcc + q * 4];

#define STORE_TILE(p)                                                          \
    do {                                                                       \
        __nv_bfloat16* pAh = sm + SAH_OFF + (p) * 5120 + ar * 40 + ac;         \
        __nv_bfloat16* pAl = sm + SAL_OFF + (p) * 5120 + ar * 40 + ac;         \
        _Pragma("unroll")                                                      \
        for (int q = 0; q < 4; q++) {                                          \
            float vs[4] = {a4[q].x, a4[q].y, a4[q].z, a4[q].w};                \
            _Pragma("unroll")                                                  \
            for (int u = 0; u < 4; u += 2) {                                   \
                __nv_bfloat16 h0, l0, h1, l1;                                  \
                split_bf16(vs[u], h0, l0);                                     \
                split_bf16(vs[u + 1], h1, l1);                                 \
                *(__nv_bfloat162*)(pAh + q * 4 + u) = __nv_bfloat162(h0, h1);  \
                *(__nv_bfloat162*)(pAl + q * 4 + u) = __nv_bfloat162(l0, l1);  \
            }                                                                  \
        }                                                                      \
        __nv_bfloat16* pBh = sm + SBH_OFF + (p) * 2304 + brr * 72 + bcc;       \
        __nv_bfloat16* pBl = sm + SBL_OFF + (p) * 2304 + brr * 72 + bcc;       \
        _Pragma("unroll")                                                      \
        for (int q = 0; q < 2; q++) {                                          \
            float vs[4] = {b4[q].x, b4[q].y, b4[q].z, b4[q].w};                \
            _Pragma("unroll")                                                  \
            for (int u = 0; u < 4; u += 2) {                                   \
                __nv_bfloat16 h0, l0, h1, l1;                                  \
                split_bf16(vs[u], h0, l0);                                     \
                split_bf16(vs[u + 1], h1, l1);                                 \
                *(__nv_bfloat162*)(pBh + q * 4 + u) = __nv_bfloat162(h0, h1);  \
                *(__nv_bfloat162*)(pBl + q * 4 + u) = __nv_bfloat162(l0, l1);  \
            }                                                                  \
        }                                                                      \
    } while (0)

    STORE_TILE(0);
    __syncthreads();

#pragma unroll
    for (int it = 0; it < INC / GBK; it++) {
        int p = it & 1;
        if (it < INC / GBK - 1) {
            int k0 = (it + 1) * GBK;
#pragma unroll
            for (int q = 0; q < 4; q++) {
                a4[q] = make_float4(0.f, 0.f, 0.f, 0.f);
                if (agr < Nn)
                    a4[q] = *(const float4*)&A[(size_t)agr * INC + k0 + ac + q * 4];
            }
#pragma unroll
            for (int q = 0; q < 2; q++)
                b4[q] = *(const float4*)&B[(size_t)(k0 + brr) * HC + bcol + bcc + q * 4];
        }

        const __nv_bfloat16* bAh = sm + SAH_OFF + p * 5120;
        const __nv_bfloat16* bAl = sm + SAL_OFF + p * 5120;
        const __nv_bfloat16* bBh = sm + SBH_OFF + p * 2304;
        const __nv_bfloat16* bBl = sm + SBL_OFF + p * 2304;
#pragma unroll
        for (int ks = 0; ks < 2; ks++) {
            unsigned Ah[2][4], Al[2][4], Bh[2][4], Bl[2][4];
            int akk = ks * 16 + (lane >> 4) * 8;
#pragma unroll
            for (int mt = 0; mt < 2; mt++) {
                int r = wm * 32 + mt * 16 + (lane & 15);
                ldsm4(Ah[mt], bAh + r * 40 + akk);
                ldsm4(Al[mt], bAl + r * 40 + akk);
            }
            int bkr = ks * 16 + ((lane >> 3) & 1) * 8 + (lane & 7);
#pragma unroll
            for (int pp = 0; pp < 2; pp++) {
                int bnc = wn * 32 + pp * 16 + (lane >> 4) * 8;
                ldsm4t(Bh[pp], bBh + bkr * 72 + bnc);
                ldsm4t(Bl[pp], bBl + bkr * 72 + bnc);
            }
#pragma unroll
            for (int mt = 0; mt < 2; mt++)
#pragma unroll
                for (int nt = 0; nt < 4; nt++) {
                    int pp = nt >> 1, i0 = (nt & 1) * 2;
                    mma16816(acc[mt][nt], Ah[mt], Bh[pp][i0], Bh[pp][i0 + 1]);
                    mma16816(acc[mt][nt], Ah[mt], Bl[pp][i0], Bl[pp][i0 + 1]);
                    mma16816(acc[mt][nt], Al[mt], Bh[pp][i0], Bh[pp][i0 + 1]);
                }
        }

        if (it < INC / GBK - 1) {
            STORE_TILE(p ^ 1);
            __syncthreads();
        }
    }

#pragma unroll
    for (int mt = 0; mt < 2; mt++) {
        int r0 = brow + wm * 32 + mt * 16 + (lane >> 2);
#pragma unroll
        for (int nt = 0; nt < 4; nt++) {
            int c = bcol + wn * 32 + nt * 8 + (lane & 3) * 2;
            if (r0 < Nn)
                *(float2*)&g_xh[(size_t)r0 * HC + c] =
                    make_float2(acc[mt][nt][0], acc[mt][nt][1]);
            if (r0 + 8 < Nn)
                *(float2*)&g_xh[(size_t)(r0 + 8) * HC + c] =
                    make_float2(acc[mt][nt][2], acc[mt][nt][3]);
        }
    }
}

// ---------------- K3: logits + fp16 copy (warp per node) -------------------
__global__ void k_logits(const float* __restrict__ att_src,
                         const float* __restrict__ att_dst, int Nn) {
    int w    = (blockIdx.x * blockDim.x + threadIdx.x) >> 5;
    int lane = threadIdx.x & 31;
    if (w >= Nn) return;
    int cb = lane * 8;
    float4 v0 = *(const float4*)&g_xh[(size_t)w * HC + cb];
    float4 v1 = *(const float4*)&g_xh[(size_t)w * HC + cb + 4];

    // fp16 copy for the aggregation gather
    __half2 p0 = __floats2half2_rn(v0.x, v0.y);
    __half2 p1 = __floats2half2_rn(v0.z, v0.w);
    __half2 p2 = __floats2half2_rn(v1.x, v1.y);
    __half2 p3 = __floats2half2_rn(v1.z, v1.w);
    uint4 pk = make_uint4(*(unsigned*)&p0, *(unsigned*)&p1,
                          *(unsigned*)&p2, *(unsigned*)&p3);
    *(uint4*)&g_xhh[(size_t)w * HC + cb] = pk;

    float4 s0 = *(const float4*)&att_src[cb];
    float4 s1 = *(const float4*)&att_src[cb + 4];
    float4 d0 = *(const float4*)&att_dst[cb];
    float4 d1 = *(const float4*)&att_dst[cb + 4];
    float s = v0.x * s0.x + v0.y * s0.y + v0.z * s0.z + v0.w * s0.w
            + v1.x * s1.x + v1.y * s1.y + v1.z * s1.z + v1.w * s1.w;
    float d = v0.x * d0.x + v0.y * d0.y + v0.z * d0.z + v0.w * d0.w
            + v1.x * d1.x + v1.y * d1.y + v1.z * d1.z + v1.w * d1.w;
    s += __shfl_xor_sync(0xFFFFFFFFu, s, 1);
    s += __shfl_xor_sync(0xFFFFFFFFu, s, 2);
    d += __shfl_xor_sync(0xFFFFFFFFu, d, 1);
    d += __shfl_xor_sync(0xFFFFFFFFu, d, 2);
    if ((lane & 3) == 0) {
        g_asrc[w * NHEAD + (lane >> 2)] = s;
        g_adst[w * NHEAD + (lane >> 2)] = d;
    }
}

// ---------------- K4: exclusive scan -> CSR offsets (warp-shuffle) ---------
__global__ void k_scan(int Nn) {
    __shared__ int wsum[32];
    __shared__ int carry;
    int tid = threadIdx.x, lane = tid & 31, wid = tid >> 5;
    if (tid == 0) { carry = 0; g_off[0] = 0; }
    __syncthreads();
    for (int base = 0; base < Nn; base += 1024) {
        int i = base + tid;
        int v = (i < Nn) ? g_cnt[i] : 0;
        int sv = v;
#pragma unroll
        for (int o = 1; o < 32; o <<= 1) {
            int t = __shfl_up_sync(0xFFFFFFFFu, sv, o);
            if (lane >= o) sv += t;
        }
        if (lane == 31) wsum[wid] = sv;
        __syncthreads();
        if (wid == 0) {
            int ws = wsum[lane];
#pragma unroll
            for (int o = 1; o < 32; o <<= 1) {
                int t = __shfl_up_sync(0xFFFFFFFFu, ws, o);
                if (lane >= o) ws += t;
            }
            wsum[lane] = ws;
        }
        __syncthreads();
        int add = carry + (wid > 0 ? wsum[wid - 1] : 0);
        if (i < Nn) g_off[i + 1] = sv + add;
        __syncthreads();
        if (tid == 0) carry += wsum[31];
        __syncthreads();
    }
}

// ---------------- K5: scatter (src, edge id) into dst-sorted order ---------
__global__ void k_scatter(int E) {
    int e = blockIdx.x * blockDim.x + threadIdx.x;
    if (e >= E) return;
    int s = g_edges[e];
    int d = g_edges[E + e];
    int pos = g_off[d] + atomicAdd(&g_fill[d], 1);
    g_sedge[pos] = make_int2(s, e);
}

// ---------------- fp16 row fma ----------------------------------------------
__device__ __forceinline__ void fma8(float& a0, float& a1, float& a2, float& a3,
                                     float& a4, float& a5, float& a6, float& a7,
                                     uint4 p, float w) {
    float2 f0 = __half22float2(*(__half2*)&p.x);
    float2 f1 = __half22float2(*(__half2*)&p.y);
    float2 f2 = __half22float2(*(__half2*)&p.z);
    float2 f3 = __half22float2(*(__half2*)&p.w);
    a0 += w * f0.x; a1 += w * f0.y; a2 += w * f1.x; a3 += w * f1.y;
    a4 += w * f2.x; a5 += w * f2.y; a6 += w * f3.x; a7 += w * f3.y;
}

// ---------------- K6: warp/node softmax + aggregation + alpha ---------------
__global__ __launch_bounds__(256) void k_agg(const float* __restrict__ x,
                                             const float* __restrict__ bias,
                                             float* __restrict__ out,
                                             float* __restrict__ alpha_out,
                                             int Nn, int E) {
    int d    = (blockIdx.x * blockDim.x + threadIdx.x) >> 5;
    int lane = threadIdx.x & 31;
    if (d >= Nn) return;
    int h  = lane >> 2;        // head for this lane's 8 channels
    int cb = lane * 8;         // channel base

    float adst_h = __ldg(&g_adst[d * NHEAD + h]);

    // self loop (fp32 row)
    float e0 = __ldg(&g_asrc[d * NHEAD + h]) + adst_h;
    e0 = (e0 > 0.f) ? e0 : 0.2f * e0;
    float ex = __expf(e0);
    float dn = ex;
    float4 v0 = __ldg((const float4*)&g_xh[(size_t)d * HC + cb]);
    float4 v1 = __ldg((const float4*)&g_xh[(size_t)d * HC + cb + 4]);
    float a0 = ex * v0.x, a1 = ex * v0.y, a2 = ex * v0.z, a3 = ex * v0.w;
    float a4 = ex * v1.x, a5 = ex * v1.y, a6 = ex * v1.z, a7 = ex * v1.w;

    int beg = g_off[d], end = g_off[d + 1];
    int j = beg;
    for (; j + 1 < end; j += 2) {
        int2 sa = __ldg(&g_sedge[j]);
        int2 sb = __ldg(&g_sedge[j + 1]);
        float ea = __ldg(&g_asrc[sa.x * NHEAD + h]) + adst_h;
        float eb = __ldg(&g_asrc[sb.x * NHEAD + h]) + adst_h;
        uint4 pa = __ldg((const uint4*)&g_xhh[(size_t)sa.x * HC + cb]);
        uint4 pb = __ldg((const uint4*)&g_xhh[(size_t)sb.x * HC + cb]);
        ea = (ea > 0.f) ? ea : 0.2f * ea;
        eb = (eb > 0.f) ? eb : 0.2f * eb;
        float wa = __expf(ea);
        float wb = __expf(eb);
        dn += wa + wb;
        fma8(a0, a1, a2, a3, a4, a5, a6, a7, pa, wa);
        fma8(a0, a1, a2, a3, a4, a5, a6, a7, pb, wb);
    }
    if (j < end) {
        int2 sa = __ldg(&g_sedge[j]);
        float ea = __ldg(&g_asrc[sa.x * NHEAD + h]) + adst_h;
        ea = (ea > 0.f) ? ea : 0.2f * ea;
        float wa = __expf(ea);
        dn += wa;
        uint4 pa = __ldg((const uint4*)&g_xhh[(size_t)sa.x * HC + cb]);
        fma8(a0, a1, a2, a3, a4, a5, a6, a7, pa, wa);
    }

    float inv = 1.f / (dn + 1e-16f);
    float4 xb0 = __ldg((const float4*)&x[(size_t)d * HC + cb]);
    float4 xb1 = __ldg((const float4*)&x[(size_t)d * HC + cb + 4]);
    float4 b0  = __ldg((const float4*)&bias[cb]);
    float4 b1  = __ldg((const float4*)&bias[cb + 4]);
    float4 o0 = make_float4(a0 * inv + xb0.x + b0.x, a1 * inv + xb0.y + b0.y,
                            a2 * inv + xb0.z + b0.z, a3 * inv + xb0.w + b0.w);
    float4 o1 = make_float4(a4 * inv + xb1.x + b1.x, a5 * inv + xb1.y + b1.y,
                            a6 * inv + xb1.z + b1.z, a7 * inv + xb1.w + b1.w);
    *(float4*)&out[(size_t)d * HC + cb]     = o0;
    *(float4*)&out[(size_t)d * HC + cb + 4] = o1;

    // ---- alpha pass: 4 edges per iteration, 8 lanes (heads) per edge ----
    if (alpha_out) {
        int hh = lane & 7;
        float dnh = __shfl_sync(0xFFFFFFFFu, dn, hh * 4) + 1e-16f;
        float adst8 = __ldg(&g_adst[d * NHEAD + hh]);
        if (lane < 8) {
            float es = __ldg(&g_asrc[d * NHEAD + hh]) + adst8;
            es = (es > 0.f) ? es : 0.2f * es;
            alpha_out[(size_t)(E + d) * NHEAD + hh] = __expf(es) / dnh;
        }
        for (int jj = beg + (lane >> 3); jj < end; jj += 4) {
            int2 se = __ldg(&g_sedge[jj]);
            float e = __ldg(&g_asrc[se.x * NHEAD + hh]) + adst8;
            e = (e > 0.f) ? e : 0.2f * e;
            alpha_out[(size_t)se.y * NHEAD + hh] = __expf(e) / dnh;
        }
    }
}

// ---------------- host launcher ---------------------------------------------
extern "C" void kernel_launch(void* const* d_in, const int* in_sizes, int n_in,
                              void* d_out, int out_size) {
    const float* x       = (const float*)d_in[0];
    const void*  ei      = d_in[1];
    const float* W       = (const float*)d_in[2];
    const float* att_src = (const float*)d_in[3];
    const float* att_dst = (const float*)d_in[4];
    const float* bias    = (const float*)d_in[5];

    int Nn   = in_sizes[0] / INC;
    int E    = in_sizes[1] / 2;
    int Etot = E + Nn;

    float* out = (float*)d_out;
    float* alpha_out = nullptr;
    if ((long long)out_size >= (long long)Nn * HC + (long long)Etot * NHEAD)
        alpha_out = out + (size_t)Nn * HC;

    // one-time host objects (no device memory involved)
    static cudaStream_t s1 = nullptr;
    static cudaEvent_t  evFork = nullptr, evJoin = nullptr;
    static int          inited = 0;
    if (!inited) {
        cudaStreamCreateWithFlags(&s1, cudaStreamNonBlocking);
        cudaEventCreateWithFlags(&evFork, cudaEventDisableTiming);
        cudaEventCreateWithFlags(&evJoin, cudaEventDisableTiming);
        cudaFuncSetAttribute(k_gemm, cudaFuncAttributeMaxDynamicSharedMemorySize,
                             SMEM_ELEMS * 2);
        inited = 1;
    }

    // fork: branch stream s1 runs GEMM + logits, main stream builds CSR
    cudaEventRecord(evFork, 0);
    cudaStreamWaitEvent(s1, evFork, 0);

    // --- branch A (s1): projection GEMM + per-node logits/fp16 copy ---
    dim3 ggrid((Nn + GBM - 1) / GBM, HC / GBN);
    k_gemm<<<ggrid, 256, SMEM_ELEMS * 2, s1>>>(x, W, Nn);
    k_logits<<<(Nn * 32 + 255) / 256, 256, 0, s1>>>(att_src, att_dst, Nn);

    // --- branch B (main stream): edge conversion + CSR build ---
    k_detect<<<1, 256>>>((const int*)ei, 16384);
    k_zero<<<(Nn + 255) / 256, 256>>>(Nn);
    k_convert<<<(2 * E + 255) / 256, 256>>>(ei, 2 * E, E);
    k_scan<<<1, 1024>>>(Nn);
    k_scatter<<<(E + 255) / 256, 256>>>(E);

    // join: main stream waits for branch A
    cudaEventRecord(evJoin, s1);
    cudaStreamWaitEvent(0, evJoin, 0);

    // fused softmax + aggregation + residual + bias + alpha (no atomics)
    k_agg<<<(Nn * 32 + 255) / 256, 256>>>(x, bias, out, alpha_out, Nn, E);
}

// round 8
// speedup vs baseline: 2.6684x; 1.0322x over previous
#include <cuda_runtime.h>
#include <cuda_bf16.h>
#include <cuda_fp16.h>

// Problem constants (fixed shapes from the reference)
#define NMAX 50000
#define EMAX 800000
#define INC  256
#define NHEAD 8
#define CH   32
#define HC   256   // NHEAD*CH

// ---------------- scratch (static device globals; no allocs allowed) -------
__device__ __half   g_xhh[NMAX * HC];           // projected features, fp16
__device__ float    g_asrc[NMAX * NHEAD];       // per-node src logits
__device__ float    g_adst[NMAX * NHEAD];       // per-node dst logits
__device__ int      g_edges[2 * EMAX];          // converted int32 edge index
__device__ int      g_cnt[NMAX];                // in-degree histogram
__device__ int      g_fill[NMAX];               // scatter fill counters
__device__ int      g_off[NMAX + 1];            // CSR offsets
__device__ int2     g_sedge[EMAX];              // (src, orig edge id) dst-sorted
__device__ int      g_is64;

// ---------------- K0: detect int64 vs int32 edge_index ---------------------
__global__ void k_detect(const int* __restrict__ p, int n_words) {
    __shared__ int s;
    if (threadIdx.x == 0) s = 0;
    __syncthreads();
    int acc = 0;
    for (int i = 1 + 2 * (int)threadIdx.x; i < n_words; i += 2 * blockDim.x)
        acc |= p[i];
    if (acc) atomicOr(&s, 1);
    __syncthreads();
    if (threadIdx.x == 0) g_is64 = (s == 0) ? 1 : 0;
}

// ---------------- K0b: zero histogram + fill counters ----------------------
__global__ void k_zero(int Nn) {
    int i = blockIdx.x * blockDim.x + threadIdx.x;
    if (i < Nn) { g_cnt[i] = 0; g_fill[i] = 0; }
}

// ---------------- K1: convert edge index to int32 + dst histogram ----------
__global__ void k_convert(const void* __restrict__ p, int twoE, int E) {
    int i = blockIdx.x * blockDim.x + threadIdx.x;
    if (i >= twoE) return;
    int v;
    if (g_is64) v = (int)((const long long*)p)[i];
    else        v = ((const int*)p)[i];
    g_edges[i] = v;
    if (i >= E) atomicAdd(&g_cnt[v], 1);   // dst half -> in-degree histogram
}

// ---------------- MMA helpers ----------------------------------------------
__device__ __forceinline__ void ldsm4(unsigned r[4], const void* p) {
    unsigned a = (unsigned)__cvta_generic_to_shared(p);
    asm volatile("ldmatrix.sync.aligned.m8n8.x4.shared.b16 {%0,%1,%2,%3}, [%4];"
                 : "=r"(r[0]), "=r"(r[1]), "=r"(r[2]), "=r"(r[3]) : "r"(a));
}
__device__ __forceinline__ void ldsm4t(unsigned r[4], const void* p) {
    unsigned a = (unsigned)__cvta_generic_to_shared(p);
    asm volatile("ldmatrix.sync.aligned.m8n8.x4.trans.shared.b16 {%0,%1,%2,%3}, [%4];"
                 : "=r"(r[0]), "=r"(r[1]), "=r"(r[2]), "=r"(r[3]) : "r"(a));
}
__device__ __forceinline__ void mma16816(float c[4], const unsigned a[4],
                                         unsigned b0, unsigned b1) {
    asm volatile(
        "mma.sync.aligned.m16n8k16.row.col.f32.bf16.bf16.f32 "
        "{%0,%1,%2,%3}, {%4,%5,%6,%7}, {%8,%9}, {%0,%1,%2,%3};"
        : "+f"(c[0]), "+f"(c[1]), "+f"(c[2]), "+f"(c[3])
        : "r"(a[0]), "r"(a[1]), "r"(a[2]), "r"(a[3]), "r"(b0), "r"(b1));
}
__device__ __forceinline__ void split_bf16(float v, __nv_bfloat16& h, __nv_bfloat16& l) {
    h = __float2bfloat16(v);
    l = __float2bfloat16(v - __bfloat162float(h));
}

// ---------------- K2: xh = x @ W  -- double-buffered bf16 split MMA --------
#define GBM 128
#define GBN 64
#define GBK 32
#define SAH_OFF 0              // [2][128][40]
#define SAL_OFF 10240
#define SBH_OFF 20480          // [2][32][72]
#define SBL_OFF 25088
#define SMEM_ELEMS 29696       // * 2B = 59392 bytes

__global__ __launch_bounds__(256, 2) void k_gemm(const float* __restrict__ A,
                                                 const float* __restrict__ B,
                                                 int Nn) {
    extern __shared__ __nv_bfloat16 sm[];

    int tid  = threadIdx.x;
    int lane = tid & 31;
    int warp = tid >> 5;
    int wm = warp & 3, wn = warp >> 2;
    int brow = blockIdx.x * GBM;
    int bcol = blockIdx.y * GBN;

    float acc[2][4][4];
#pragma unroll
    for (int i = 0; i < 2; i++)
#pragma unroll
        for (int j = 0; j < 4; j++)
#pragma unroll
            for (int k = 0; k < 4; k++) acc[i][j][k] = 0.f;

    int ar  = tid >> 1;
    int ac  = (tid & 1) * 16;
    int agr = brow + ar;
    int brr = tid >> 3;
    int bcc = (tid & 7) * 8;

    float4 a4[4], b4[2];

#pragma unroll
    for (int q = 0; q < 4; q++) {
        a4[q] = make_float4(0.f, 0.f, 0.f, 0.f);
        if (agr < Nn) a4[q] = *(const float4*)&A[(size_t)agr * INC + ac + q * 4];
    }
#pragma unroll
    for (int q = 0; q < 2; q++)
        b4[q] = *(const float4*)&B[(size_t)brr * HC + bcol + bcc + q * 4];

#define STORE_TILE(p)                                                          \
    do {                                                                       \
        __nv_bfloat16* pAh = sm + SAH_OFF + (p) * 5120 + ar * 40 + ac;         \
        __nv_bfloat16* pAl = sm + SAL_OFF + (p) * 5120 + ar * 40 + ac;         \
        _Pragma("unroll")                                                      \
        for (int q = 0; q < 4; q++) {                                          \
            float vs[4] = {a4[q].x, a4[q].y, a4[q].z, a4[q].w};                \
            _Pragma("unroll")                                                  \
            for (int u = 0; u < 4; u += 2) {                                   \
                __nv_bfloat16 h0, l0, h1, l1;                                  \
                split_bf16(vs[u], h0, l0);                                     \
                split_bf16(vs[u + 1], h1, l1);                                 \
                *(__nv_bfloat162*)(pAh + q * 4 + u) = __nv_bfloat162(h0, h1);  \
                *(__nv_bfloat162*)(pAl + q * 4 + u) = __nv_bfloat162(l0, l1);  \
            }                                                                  \
        }                                                                      \
        __nv_bfloat16* pBh = sm + SBH_OFF + (p) * 2304 + brr * 72 + bcc;       \
        __nv_bfloat16* pBl = sm + SBL_OFF + (p) * 2304 + brr * 72 + bcc;       \
        _Pragma("unroll")                                                      \
        for (int q = 0; q < 2; q++) {                                          \
            float vs[4] = {b4[q].x, b4[q].y, b4[q].z, b4[q].w};                \
            _Pragma("unroll")                                                  \
            for (int u = 0; u < 4; u += 2) {                                   \
                __nv_bfloat16 h0, l0, h1, l1;                                  \
                split_bf16(vs[u], h0, l0);                                     \
                split_bf16(vs[u + 1], h1, l1);                                 \
                *(__nv_bfloat162*)(pBh + q * 4 + u) = __nv_bfloat162(h0, h1);  \
                *(__nv_bfloat162*)(pBl + q * 4 + u) = __nv_bfloat162(l0, l1);  \
            }                                                                  \
        }                                                                      \
    } while (0)

    STORE_TILE(0);
    __syncthreads();

#pragma unroll
    for (int it = 0; it < INC / GBK; it++) {
        int p = it & 1;
        if (it < INC / GBK - 1) {
            int k0 = (it + 1) * GBK;
#pragma unroll
            for (int q = 0; q < 4; q++) {
                a4[q] = make_float4(0.f, 0.f, 0.f, 0.f);
                if (agr < Nn)
                    a4[q] = *(const float4*)&A[(size_t)agr * INC + k0 + ac + q * 4];
            }
#pragma unroll
            for (int q = 0; q < 2; q++)
                b4[q] = *(const float4*)&B[(size_t)(k0 + brr) * HC + bcol + bcc + q * 4];
        }

        const __nv_bfloat16* bAh = sm + SAH_OFF + p * 5120;
        const __nv_bfloat16* bAl = sm + SAL_OFF + p * 5120;
        const __nv_bfloat16* bBh = sm + SBH_OFF + p * 2304;
        const __nv_bfloat16* bBl = sm + SBL_OFF + p * 2304;
#pragma unroll
        for (int ks = 0; ks < 2; ks++) {
            unsigned Ah[2][4], Al[2][4], Bh[2][4], Bl[2][4];
            int akk = ks * 16 + (lane >> 4) * 8;
#pragma unroll
            for (int mt = 0; mt < 2; mt++) {
                int r = wm * 32 + mt * 16 + (lane & 15);
                ldsm4(Ah[mt], bAh + r * 40 + akk);
                ldsm4(Al[mt], bAl + r * 40 + akk);
            }
            int bkr = ks * 16 + ((lane >> 3) & 1) * 8 + (lane & 7);
#pragma unroll
            for (int pp = 0; pp < 2; pp++) {
                int bnc = wn * 32 + pp * 16 + (lane >> 4) * 8;
                ldsm4t(Bh[pp], bBh + bkr * 72 + bnc);
                ldsm4t(Bl[pp], bBl + bkr * 72 + bnc);
            }
#pragma unroll
            for (int mt = 0; mt < 2; mt++)
#pragma unroll
                for (int nt = 0; nt < 4; nt++) {
                    int pp = nt >> 1, i0 = (nt & 1) * 2;
                    mma16816(acc[mt][nt], Ah[mt], Bh[pp][i0], Bh[pp][i0 + 1]);
                    mma16816(acc[mt][nt], Ah[mt], Bl[pp][i0], Bl[pp][i0 + 1]);
                    mma16816(acc[mt][nt], Al[mt], Bh[pp][i0], Bh[pp][i0 + 1]);
                }
        }

        if (it < INC / GBK - 1) {
            STORE_TILE(p ^ 1);
            __syncthreads();
        }
    }

    // epilogue: store fp16 directly
#pragma unroll
    for (int mt = 0; mt < 2; mt++) {
        int r0 = brow + wm * 32 + mt * 16 + (lane >> 2);
#pragma unroll
        for (int nt = 0; nt < 4; nt++) {
            int c = bcol + wn * 32 + nt * 8 + (lane & 3) * 2;
            if (r0 < Nn) {
                __half2 hv = __floats2half2_rn(acc[mt][nt][0], acc[mt][nt][1]);
                *(__half2*)&g_xhh[(size_t)r0 * HC + c] = hv;
            }
            if (r0 + 8 < Nn) {
                __half2 hv = __floats2half2_rn(acc[mt][nt][2], acc[mt][nt][3]);
                *(__half2*)&g_xhh[(size_t)(r0 + 8) * HC + c] = hv;
            }
        }
    }
}

// ---------------- K3: logits from fp16 features (warp per node) ------------
__global__ void k_logits(const float* __restrict__ att_src,
                         const float* __restrict__ att_dst, int Nn) {
    int w    = (blockIdx.x * blockDim.x + threadIdx.x) >> 5;
    int lane = threadIdx.x & 31;
    if (w >= Nn) return;
    int cb = lane * 8;
    uint4 pk = *(const uint4*)&g_xhh[(size_t)w * HC + cb];
    float2 f0 = __half22float2(*(__half2*)&pk.x);
    float2 f1 = __half22float2(*(__half2*)&pk.y);
    float2 f2 = __half22float2(*(__half2*)&pk.z);
    float2 f3 = __half22float2(*(__half2*)&pk.w);

    float4 s0 = *(const float4*)&att_src[cb];
    float4 s1 = *(const float4*)&att_src[cb + 4];
    float4 d0 = *(const float4*)&att_dst[cb];
    float4 d1 = *(const float4*)&att_dst[cb + 4];
    float s = f0.x * s0.x + f0.y * s0.y + f1.x * s0.z + f1.y * s0.w
            + f2.x * s1.x + f2.y * s1.y + f3.x * s1.z + f3.y * s1.w;
    float d = f0.x * d0.x + f0.y * d0.y + f1.x * d0.z + f1.y * d0.w
            + f2.x * d1.x + f2.y * d1.y + f3.x * d1.z + f3.y * d1.w;
    s += __shfl_xor_sync(0xFFFFFFFFu, s, 1);
    s += __shfl_xor_sync(0xFFFFFFFFu, s, 2);
    d += __shfl_xor_sync(0xFFFFFFFFu, d, 1);
    d += __shfl_xor_sync(0xFFFFFFFFu, d, 2);
    if ((lane & 3) == 0) {
        g_asrc[w * NHEAD + (lane >> 2)] = s;
        g_adst[w * NHEAD + (lane >> 2)] = d;
    }
}

// ---------------- K4: exclusive scan -> CSR offsets (warp-shuffle) ---------
__global__ void k_scan(int Nn) {
    __shared__ int wsum[32];
    __shared__ int carry;
    int tid = threadIdx.x, lane = tid & 31, wid = tid >> 5;
    if (tid == 0) { carry = 0; g_off[0] = 0; }
    __syncthreads();
    for (int base = 0; base < Nn; base += 1024) {
        int i = base + tid;
        int v = (i < Nn) ? g_cnt[i] : 0;
        int sv = v;
#pragma unroll
        for (int o = 1; o < 32; o <<= 1) {
            int t = __shfl_up_sync(0xFFFFFFFFu, sv, o);
            if (lane >= o) sv += t;
        }
        if (lane == 31) wsum[wid] = sv;
        __syncthreads();
        if (wid == 0) {
            int ws = wsum[lane];
#pragma unroll
            for (int o = 1; o < 32; o <<= 1) {
                int t = __shfl_up_sync(0xFFFFFFFFu, ws, o);
                if (lane >= o) ws += t;
            }
            wsum[lane] = ws;
        }
        __syncthreads();
        int add = carry + (wid > 0 ? wsum[wid - 1] : 0);
        if (i < Nn) g_off[i + 1] = sv + add;
        __syncthreads();
        if (tid == 0) carry += wsum[31];
        __syncthreads();
    }
}

// ---------------- K5: scatter (src, edge id) into dst-sorted order ---------
__global__ void k_scatter(int E) {
    int e = blockIdx.x * blockDim.x + threadIdx.x;
    if (e >= E) return;
    int s = g_edges[e];
    int d = g_edges[E + e];
    int pos = g_off[d] + atomicAdd(&g_fill[d], 1);
    g_sedge[pos] = make_int2(s, e);
}

// ---------------- fp16 row fma ----------------------------------------------
__device__ __forceinline__ void fma8(float& a0, float& a1, float& a2, float& a3,
                                     float& a4, float& a5, float& a6, float& a7,
                                     uint4 p, float w) {
    float2 f0 = __half22float2(*(__half2*)&p.x);
    float2 f1 = __half22float2(*(__half2*)&p.y);
    float2 f2 = __half22float2(*(__half2*)&p.z);
    float2 f3 = __half22float2(*(__half2*)&p.w);
    a0 += w * f0.x; a1 += w * f0.y; a2 += w * f1.x; a3 += w * f1.y;
    a4 += w * f2.x; a5 += w * f2.y; a6 += w * f3.x; a7 += w * f3.y;
}

// ---------------- K6: warp/node softmax + aggregation + alpha ---------------
__global__ __launch_bounds__(256) void k_agg(const float* __restrict__ x,
                                             const float* __restrict__ bias,
                                             float* __restrict__ out,
                                             float* __restrict__ alpha_out,
                                             int Nn, int E) {
    int d    = (blockIdx.x * blockDim.x + threadIdx.x) >> 5;
    int lane = threadIdx.x & 31;
    if (d >= Nn) return;
    int h  = lane >> 2;        // head for this lane's 8 channels
    int cb = lane * 8;         // channel base

    float adst_h = __ldg(&g_adst[d * NHEAD + h]);

    // self loop
    float e0 = __ldg(&g_asrc[d * NHEAD + h]) + adst_h;
    e0 = (e0 > 0.f) ? e0 : 0.2f * e0;
    float ex = __expf(e0);
    float dn = ex;
    float a0 = 0.f, a1 = 0.f, a2 = 0.f, a3 = 0.f,
          a4 = 0.f, a5 = 0.f, a6 = 0.f, a7 = 0.f;
    {
        uint4 pd = __ldg((const uint4*)&g_xhh[(size_t)d * HC + cb]);
        fma8(a0, a1, a2, a3, a4, a5, a6, a7, pd, ex);
    }

    int beg = g_off[d], end = g_off[d + 1];
    int j = beg;
    // 4-edge unrolled main loop (MLP ~12)
    for (; j + 3 < end; j += 4) {
        int2 s0 = __ldg(&g_sedge[j]);
        int2 s1 = __ldg(&g_sedge[j + 1]);
        int2 s2 = __ldg(&g_sedge[j + 2]);
        int2 s3 = __ldg(&g_sedge[j + 3]);
        float e0a = __ldg(&g_asrc[s0.x * NHEAD + h]) + adst_h;
        float e1a = __ldg(&g_asrc[s1.x * NHEAD + h]) + adst_h;
        float e2a = __ldg(&g_asrc[s2.x * NHEAD + h]) + adst_h;
        float e3a = __ldg(&g_asrc[s3.x * NHEAD + h]) + adst_h;
        uint4 p0 = __ldg((const uint4*)&g_xhh[(size_t)s0.x * HC + cb]);
        uint4 p1 = __ldg((const uint4*)&g_xhh[(size_t)s1.x * HC + cb]);
        uint4 p2 = __ldg((const uint4*)&g_xhh[(size_t)s2.x * HC + cb]);
        uint4 p3 = __ldg((const uint4*)&g_xhh[(size_t)s3.x * HC + cb]);
        e0a = (e0a > 0.f) ? e0a : 0.2f * e0a;
        e1a = (e1a > 0.f) ? e1a : 0.2f * e1a;
        e2a = (e2a > 0.f) ? e2a : 0.2f * e2a;
        e3a = (e3a > 0.f) ? e3a : 0.2f * e3a;
        float w0 = __expf(e0a), w1 = __expf(e1a);
        float w2 = __expf(e2a), w3 = __expf(e3a);
        dn += (w0 + w1) + (w2 + w3);
        fma8(a0, a1, a2, a3, a4, a5, a6, a7, p0, w0);
        fma8(a0, a1, a2, a3, a4, a5, a6, a7, p1, w1);
        fma8(a0, a1, a2, a3, a4, a5, a6, a7, p2, w2);
        fma8(a0, a1, a2, a3, a4, a5, a6, a7, p3, w3);
    }
    for (; j < end; j++) {
        int2 sa = __ldg(&g_sedge[j]);
        float ea = __ldg(&g_asrc[sa.x * NHEAD + h]) + adst_h;
        ea = (ea > 0.f) ? ea : 0.2f * ea;
        float wa = __expf(ea);
        dn += wa;
        uint4 pa = __ldg((const uint4*)&g_xhh[(size_t)sa.x * HC + cb]);
        fma8(a0, a1, a2, a3, a4, a5, a6, a7, pa, wa);
    }

    float inv = 1.f / (dn + 1e-16f);
    float4 xb0 = __ldg((const float4*)&x[(size_t)d * HC + cb]);
    float4 xb1 = __ldg((const float4*)&x[(size_t)d * HC + cb + 4]);
    float4 b0  = __ldg((const float4*)&bias[cb]);
    float4 b1  = __ldg((const float4*)&bias[cb + 4]);
    float4 o0 = make_float4(a0 * inv + xb0.x + b0.x, a1 * inv + xb0.y + b0.y,
                            a2 * inv + xb0.z + b0.z, a3 * inv + xb0.w + b0.w);
    float4 o1 = make_float4(a4 * inv + xb1.x + b1.x, a5 * inv + xb1.y + b1.y,
                            a6 * inv + xb1.z + b1.z, a7 * inv + xb1.w + b1.w);
    *(float4*)&out[(size_t)d * HC + cb]     = o0;
    *(float4*)&out[(size_t)d * HC + cb + 4] = o1;

    // ---- alpha pass: 4 edges per iteration, 8 lanes (heads) per edge ----
    if (alpha_out) {
        int hh = lane & 7;
        float dnh = __shfl_sync(0xFFFFFFFFu, dn, hh * 4) + 1e-16f;
        float adst8 = __ldg(&g_adst[d * NHEAD + hh]);
        if (lane < 8) {
            float es = __ldg(&g_asrc[d * NHEAD + hh]) + adst8;
            es = (es > 0.f) ? es : 0.2f * es;
            alpha_out[(size_t)(E + d) * NHEAD + hh] = __expf(es) / dnh;
        }
        for (int jj = beg + (lane >> 3); jj < end; jj += 4) {
            int2 se = __ldg(&g_sedge[jj]);
            float e = __ldg(&g_asrc[se.x * NHEAD + hh]) + adst8;
            e = (e > 0.f) ? e : 0.2f * e;
            alpha_out[(size_t)se.y * NHEAD + hh] = __expf(e) / dnh;
        }
    }
}

// ---------------- host launcher ---------------------------------------------
extern "C" void kernel_launch(void* const* d_in, const int* in_sizes, int n_in,
                              void* d_out, int out_size) {
    const float* x       = (const float*)d_in[0];
    const void*  ei      = d_in[1];
    const float* W       = (const float*)d_in[2];
    const float* att_src = (const float*)d_in[3];
    const float* att_dst = (const float*)d_in[4];
    const float* bias    = (const float*)d_in[5];

    int Nn   = in_sizes[0] / INC;
    int E    = in_sizes[1] / 2;
    int Etot = E + Nn;

    float* out = (float*)d_out;
    float* alpha_out = nullptr;
    if ((long long)out_size >= (long long)Nn * HC + (long long)Etot * NHEAD)
        alpha_out = out + (size_t)Nn * HC;

    // one-time host objects (no device memory involved)
    static cudaStream_t s1 = nullptr;
    static cudaEvent_t  evFork = nullptr, evJoin = nullptr;
    static int          inited = 0;
    if (!inited) {
        cudaStreamCreateWithFlags(&s1, cudaStreamNonBlocking);
        cudaEventCreateWithFlags(&evFork, cudaEventDisableTiming);
        cudaEventCreateWithFlags(&evJoin, cudaEventDisableTiming);
        cudaFuncSetAttribute(k_gemm, cudaFuncAttributeMaxDynamicSharedMemorySize,
                             SMEM_ELEMS * 2);
        inited = 1;
    }

    // fork: branch stream s1 runs GEMM + logits, main stream builds CSR
    cudaEventRecord(evFork, 0);
    cudaStreamWaitEvent(s1, evFork, 0);

    // --- branch A (s1): projection GEMM + per-node logits ---
    dim3 ggrid((Nn + GBM - 1) / GBM, HC / GBN);
    k_gemm<<<ggrid, 256, SMEM_ELEMS * 2, s1>>>(x, W, Nn);
    k_logits<<<(Nn * 32 + 255) / 256, 256, 0, s1>>>(att_src, att_dst, Nn);

    // --- branch B (main stream): edge conversion + CSR build ---
    k_detect<<<1, 256>>>((const int*)ei, 16384);
    k_zero<<<(Nn + 255) / 256, 256>>>(Nn);
    k_convert<<<(2 * E + 255) / 256, 256>>>(ei, 2 * E, E);
    k_scan<<<1, 1024>>>(Nn);
    k_scatter<<<(E + 255) / 256, 256>>>(E);

    // join: main stream waits for branch A
    cudaEventRecord(evJoin, s1);
    cudaStreamWaitEvent(0, evJoin, 0);

    // fused softmax + aggregation + residual + bias + alpha (no atomics)
    k_agg<<<(Nn * 32 + 255) / 256, 256>>>(x, bias, out, alpha_out, Nn, E);
}

// round 9
// speedup vs baseline: 2.6878x; 1.0073x over previous
#include <cuda_runtime.h>
#include <cuda_bf16.h>
#include <cuda_fp16.h>

// Problem constants (fixed shapes from the reference)
#define NMAX 50000
#define EMAX 800000
#define INC  256
#define NHEAD 8
#define CH   32
#define HC   256   // NHEAD*CH

// ---------------- scratch (static device globals; no allocs allowed) -------
__device__ __half   g_xhh[NMAX * HC];           // projected features, fp16
__device__ float    g_asrc[NMAX * NHEAD];       // per-node src logits
__device__ float    g_adst[NMAX * NHEAD];       // per-node dst logits
__device__ int      g_edges[2 * EMAX];          // converted int32 edge index
__device__ int      g_cnt[NMAX];                // in-degree histogram
__device__ int      g_fill[NMAX];               // scatter fill counters
__device__ int      g_off[NMAX + 1];            // CSR offsets
__device__ int2     g_sedge[EMAX];              // (src, orig edge id) dst-sorted
__device__ int      g_is64;

// ---------------- K0: detect int64 vs int32 edge_index ---------------------
__global__ void k_detect(const int* __restrict__ p, int n_words) {
    __shared__ int s;
    if (threadIdx.x == 0) s = 0;
    __syncthreads();
    int acc = 0;
    for (int i = 1 + 2 * (int)threadIdx.x; i < n_words; i += 2 * blockDim.x)
        acc |= p[i];
    if (acc) atomicOr(&s, 1);
    __syncthreads();
    if (threadIdx.x == 0) g_is64 = (s == 0) ? 1 : 0;
}

// ---------------- K0b: zero histogram + fill counters ----------------------
__global__ void k_zero(int Nn) {
    int i = blockIdx.x * blockDim.x + threadIdx.x;
    if (i < Nn) { g_cnt[i] = 0; g_fill[i] = 0; }
}

// ---------------- K1: convert edge index to int32 + dst histogram ----------
__global__ void k_convert(const void* __restrict__ p, int twoE, int E) {
    int i = blockIdx.x * blockDim.x + threadIdx.x;
    if (i >= twoE) return;
    int v;
    if (g_is64) v = (int)((const long long*)p)[i];
    else        v = ((const int*)p)[i];
    g_edges[i] = v;
    if (i >= E) atomicAdd(&g_cnt[v], 1);   // dst half -> in-degree histogram
}

// ---------------- MMA helpers ----------------------------------------------
__device__ __forceinline__ void ldsm4(unsigned r[4], const void* p) {
    unsigned a = (unsigned)__cvta_generic_to_shared(p);
    asm volatile("ldmatrix.sync.aligned.m8n8.x4.shared.b16 {%0,%1,%2,%3}, [%4];"
                 : "=r"(r[0]), "=r"(r[1]), "=r"(r[2]), "=r"(r[3]) : "r"(a));
}
__device__ __forceinline__ void ldsm4t(unsigned r[4], const void* p) {
    unsigned a = (unsigned)__cvta_generic_to_shared(p);
    asm volatile("ldmatrix.sync.aligned.m8n8.x4.trans.shared.b16 {%0,%1,%2,%3}, [%4];"
                 : "=r"(r[0]), "=r"(r[1]), "=r"(r[2]), "=r"(r[3]) : "r"(a));
}
__device__ __forceinline__ void mma16816(float c[4], const unsigned a[4],
                                         unsigned b0, unsigned b1) {
    asm volatile(
        "mma.sync.aligned.m16n8k16.row.col.f32.bf16.bf16.f32 "
        "{%0,%1,%2,%3}, {%4,%5,%6,%7}, {%8,%9}, {%0,%1,%2,%3};"
        : "+f"(c[0]), "+f"(c[1]), "+f"(c[2]), "+f"(c[3])
        : "r"(a[0]), "r"(a[1]), "r"(a[2]), "r"(a[3]), "r"(b0), "r"(b1));
}
__device__ __forceinline__ void split_bf16(float v, __nv_bfloat16& h, __nv_bfloat16& l) {
    h = __float2bfloat16(v);
    l = __float2bfloat16(v - __bfloat162float(h));
}

// ---------------- K2: xh = x @ W  -- CTA 128x256, 512 thr, bf16 split ------
// 16 warps as 4(M) x 4(N); warp tile 32x64. A read ONCE from DRAM.
// acc = Ah*Bh + Ah*Bl + Al*Bh
#define GBM 128
#define GBK 32
// dynamic smem element offsets (bf16 elements)
#define SAH_OFF 0              // [2][128][40]
#define SAL_OFF 10240
#define SBH_OFF 20480          // [2][32][264]
#define SBL_OFF 37376
#define SMEM_ELEMS 54272       // * 2B = 108544 bytes

__global__ __launch_bounds__(512, 1) void k_gemm(const float* __restrict__ A,
                                                 const float* __restrict__ B,
                                                 int Nn) {
    extern __shared__ __nv_bfloat16 sm[];

    int tid  = threadIdx.x;
    int lane = tid & 31;
    int warp = tid >> 5;
    int wm = warp & 3, wn = warp >> 2;   // 4 x 4 warp grid
    int brow = blockIdx.x * GBM;

    float acc[2][8][4];
#pragma unroll
    for (int i = 0; i < 2; i++)
#pragma unroll
        for (int j = 0; j < 8; j++)
#pragma unroll
            for (int k = 0; k < 4; k++) acc[i][j][k] = 0.f;

    // loader coordinates
    int ar  = tid >> 3;            // A row 0..63 (+q*64)
    int ac  = (tid & 7) * 4;       // A col 0..28
    int brr = tid >> 6;            // B row 0..7 (+q*8)
    int bcc = (tid & 63) * 4;      // B col 0..252

    float4 a4[2], b4[4];

    // prologue: load k0 = 0
#pragma unroll
    for (int q = 0; q < 2; q++) {
        int gr = brow + ar + q * 64;
        a4[q] = make_float4(0.f, 0.f, 0.f, 0.f);
        if (gr < Nn) a4[q] = *(const float4*)&A[(size_t)gr * INC + ac];
    }
#pragma unroll
    for (int q = 0; q < 4; q++)
        b4[q] = *(const float4*)&B[(size_t)(brr + q * 8) * HC + bcc];

#define STORE_TILE(p)                                                          \
    do {                                                                       \
        _Pragma("unroll")                                                      \
        for (int q = 0; q < 2; q++) {                                          \
            int row = ar + q * 64;                                             \
            __nv_bfloat16* pAh = sm + SAH_OFF + (p) * 5120 + row * 40 + ac;    \
            __nv_bfloat16* pAl = sm + SAL_OFF + (p) * 5120 + row * 40 + ac;    \
            float vs[4] = {a4[q].x, a4[q].y, a4[q].z, a4[q].w};                \
            _Pragma("unroll")                                                  \
            for (int u = 0; u < 4; u += 2) {                                   \
                __nv_bfloat16 h0, l0, h1, l1;                                  \
                split_bf16(vs[u], h0, l0);                                     \
                split_bf16(vs[u + 1], h1, l1);                                 \
                *(__nv_bfloat162*)(pAh + u) = __nv_bfloat162(h0, h1);          \
                *(__nv_bfloat162*)(pAl + u) = __nv_bfloat162(l0, l1);          \
            }                                                                  \
        }                                                                      \
        _Pragma("unroll")                                                      \
        for (int q = 0; q < 4; q++) {                                          \
            int row = brr + q * 8;                                             \
            __nv_bfloat16* pBh = sm + SBH_OFF + (p) * 8448 + row * 264 + bcc;  \
            __nv_bfloat16* pBl = sm + SBL_OFF + (p) * 8448 + row * 264 + bcc;  \
            float vs[4] = {b4[q].x, b4[q].y, b4[q].z, b4[q].w};                \
            _Pragma("unroll")                                                  \
            for (int u = 0; u < 4; u += 2) {                                   \
                __nv_bfloat16 h0, l0, h1, l1;                                  \
                split_bf16(vs[u], h0, l0);                                     \
                split_bf16(vs[u + 1], h1, l1);                                 \
                *(__nv_bfloat162*)(pBh + u) = __nv_bfloat162(h0, h1);          \
                *(__nv_bfloat162*)(pBl + u) = __nv_bfloat162(l0, l1);          \
            }                                                                  \
        }                                                                      \
    } while (0)

    STORE_TILE(0);
    __syncthreads();

#pragma unroll
    for (int it = 0; it < INC / GBK; it++) {
        int p = it & 1;
        // prefetch next K tile into registers
        if (it < INC / GBK - 1) {
            int k0 = (it + 1) * GBK;
#pragma unroll
            for (int q = 0; q < 2; q++) {
                int gr = brow + ar + q * 64;
                a4[q] = make_float4(0.f, 0.f, 0.f, 0.f);
                if (gr < Nn) a4[q] = *(const float4*)&A[(size_t)gr * INC + k0 + ac];
            }
#pragma unroll
            for (int q = 0; q < 4; q++)
                b4[q] = *(const float4*)&B[(size_t)(k0 + brr + q * 8) * HC + bcc];
        }

        const __nv_bfloat16* bAh = sm + SAH_OFF + p * 5120;
        const __nv_bfloat16* bAl = sm + SAL_OFF + p * 5120;
        const __nv_bfloat16* bBh = sm + SBH_OFF + p * 8448;
        const __nv_bfloat16* bBl = sm + SBL_OFF + p * 8448;
#pragma unroll
        for (int ks = 0; ks < 2; ks++) {
            unsigned Ah[2][4], Al[2][4];
            int akk = ks * 16 + (lane >> 4) * 8;
#pragma unroll
            for (int mt = 0; mt < 2; mt++) {
                int r = wm * 32 + mt * 16 + (lane & 15);
                ldsm4(Ah[mt], bAh + r * 40 + akk);
                ldsm4(Al[mt], bAl + r * 40 + akk);
            }
            int bkr = ks * 16 + ((lane >> 3) & 1) * 8 + (lane & 7);
            // process B in two 32-col halves to bound register pressure
#pragma unroll
            for (int hb = 0; hb < 2; hb++) {
                unsigned Bh[2][4], Bl[2][4];
#pragma unroll
                for (int pp = 0; pp < 2; pp++) {
                    int bnc = wn * 64 + hb * 32 + pp * 16 + (lane >> 4) * 8;
                    ldsm4t(Bh[pp], bBh + bkr * 264 + bnc);
                    ldsm4t(Bl[pp], bBl + bkr * 264 + bnc);
                }
#pragma unroll
                for (int mt = 0; mt < 2; mt++)
#pragma unroll
                    for (int ntl = 0; ntl < 4; ntl++) {
                        int nt = hb * 4 + ntl;
                        int pp = ntl >> 1, i0 = (ntl & 1) * 2;
                        mma16816(acc[mt][nt], Ah[mt], Bh[pp][i0], Bh[pp][i0 + 1]);
                        mma16816(acc[mt][nt], Ah[mt], Bl[pp][i0], Bl[pp][i0 + 1]);
                        mma16816(acc[mt][nt], Al[mt], Bh[pp][i0], Bh[pp][i0 + 1]);
                    }
            }
        }

        if (it < INC / GBK - 1) {
            STORE_TILE(p ^ 1);
            __syncthreads();
        }
    }

    // epilogue: store fp16 directly
#pragma unroll
    for (int mt = 0; mt < 2; mt++) {
        int r0 = brow + wm * 32 + mt * 16 + (lane >> 2);
#pragma unroll
        for (int nt = 0; nt < 8; nt++) {
            int c = wn * 64 + nt * 8 + (lane & 3) * 2;
            if (r0 < Nn) {
                __half2 hv = __floats2half2_rn(acc[mt][nt][0], acc[mt][nt][1]);
                *(__half2*)&g_xhh[(size_t)r0 * HC + c] = hv;
            }
            if (r0 + 8 < Nn) {
                __half2 hv = __floats2half2_rn(acc[mt][nt][2], acc[mt][nt][3]);
                *(__half2*)&g_xhh[(size_t)(r0 + 8) * HC + c] = hv;
            }
        }
    }
}

// ---------------- K3: logits from fp16 features (warp per node) ------------
__global__ void k_logits(const float* __restrict__ att_src,
                         const float* __restrict__ att_dst, int Nn) {
    int w    = (blockIdx.x * blockDim.x + threadIdx.x) >> 5;
    int lane = threadIdx.x & 31;
    if (w >= Nn) return;
    int cb = lane * 8;
    uint4 pk = *(const uint4*)&g_xhh[(size_t)w * HC + cb];
    float2 f0 = __half22float2(*(__half2*)&pk.x);
    float2 f1 = __half22float2(*(__half2*)&pk.y);
    float2 f2 = __half22float2(*(__half2*)&pk.z);
    float2 f3 = __half22float2(*(__half2*)&pk.w);

    float4 s0 = *(const float4*)&att_src[cb];
    float4 s1 = *(const float4*)&att_src[cb + 4];
    float4 d0 = *(const float4*)&att_dst[cb];
    float4 d1 = *(const float4*)&att_dst[cb + 4];
    float s = f0.x * s0.x + f0.y * s0.y + f1.x * s0.z + f1.y * s0.w
            + f2.x * s1.x + f2.y * s1.y + f3.x * s1.z + f3.y * s1.w;
    float d = f0.x * d0.x + f0.y * d0.y + f1.x * d0.z + f1.y * d0.w
            + f2.x * d1.x + f2.y * d1.y + f3.x * d1.z + f3.y * d1.w;
    s += __shfl_xor_sync(0xFFFFFFFFu, s, 1);
    s += __shfl_xor_sync(0xFFFFFFFFu, s, 2);
    d += __shfl_xor_sync(0xFFFFFFFFu, d, 1);
    d += __shfl_xor_sync(0xFFFFFFFFu, d, 2);
    if ((lane & 3) == 0) {
        g_asrc[w * NHEAD + (lane >> 2)] = s;
        g_adst[w * NHEAD + (lane >> 2)] = d;
    }
}

// ---------------- K4: exclusive scan -> CSR offsets (warp-shuffle) ---------
__global__ void k_scan(int Nn) {
    __shared__ int wsum[32];
    __shared__ int carry;
    int tid = threadIdx.x, lane = tid & 31, wid = tid >> 5;
    if (tid == 0) { carry = 0; g_off[0] = 0; }
    __syncthreads();
    for (int base = 0; base < Nn; base += 1024) {
        int i = base + tid;
        int v = (i < Nn) ? g_cnt[i] : 0;
        int sv = v;
#pragma unroll
        for (int o = 1; o < 32; o <<= 1) {
            int t = __shfl_up_sync(0xFFFFFFFFu, sv, o);
            if (lane >= o) sv += t;
        }
        if (lane == 31) wsum[wid] = sv;
        __syncthreads();
        if (wid == 0) {
            int ws = wsum[lane];
#pragma unroll
            for (int o = 1; o < 32; o <<= 1) {
                int t = __shfl_up_sync(0xFFFFFFFFu, ws, o);
                if (lane >= o) ws += t;
            }
            wsum[lane] = ws;
        }
        __syncthreads();
        int add = carry + (wid > 0 ? wsum[wid - 1] : 0);
        if (i < Nn) g_off[i + 1] = sv + add;
        __syncthreads();
        if (tid == 0) carry += wsum[31];
        __syncthreads();
    }
}

// ---------------- K5: scatter (src, edge id) into dst-sorted order ---------
__global__ void k_scatter(int E) {
    int e = blockIdx.x * blockDim.x + threadIdx.x;
    if (e >= E) return;
    int s = g_edges[e];
    int d = g_edges[E + e];
    int pos = g_off[d] + atomicAdd(&g_fill[d], 1);
    g_sedge[pos] = make_int2(s, e);
}

// ---------------- fp16 4-channel fma -----------------------------------------
__device__ __forceinline__ void fma4(float& a0, float& a1, float& a2, float& a3,
                                     uint2 p, float w) {
    float2 f0 = __half22float2(*(__half2*)&p.x);
    float2 f1 = __half22float2(*(__half2*)&p.y);
    a0 += w * f0.x; a1 += w * f0.y; a2 += w * f1.x; a3 += w * f1.y;
}

// ---------------- K6: 2 warps/node softmax + aggregation + alpha ------------
__global__ __launch_bounds__(256) void k_agg(const float* __restrict__ x,
                                             const float* __restrict__ bias,
                                             float* __restrict__ out,
                                             float* __restrict__ alpha_out,
                                             int Nn, int E) {
    int gw   = (blockIdx.x * blockDim.x + threadIdx.x) >> 5;
    int lane = threadIdx.x & 31;
    int d    = gw >> 1;         // node
    int hf   = gw & 1;          // channel half
    if (d >= Nn) return;
    int cb = hf * 128 + lane * 4;   // 4 channels per lane
    int h  = cb >> 5;               // head

    float adst_h = __ldg(&g_adst[d * NHEAD + h]);

    // self loop
    float e0 = __ldg(&g_asrc[d * NHEAD + h]) + adst_h;
    e0 = (e0 > 0.f) ? e0 : 0.2f * e0;
    float ex = __expf(e0);
    float dn = ex;
    float a0 = 0.f, a1 = 0.f, a2 = 0.f, a3 = 0.f;
    {
        uint2 pd = __ldg((const uint2*)&g_xhh[(size_t)d * HC + cb]);
        fma4(a0, a1, a2, a3, pd, ex);
    }

    int beg = g_off[d], end = g_off[d + 1];
    int j = beg;
    for (; j + 3 < end; j += 4) {
        int2 s0 = __ldg(&g_sedge[j]);
        int2 s1 = __ldg(&g_sedge[j + 1]);
        int2 s2 = __ldg(&g_sedge[j + 2]);
        int2 s3 = __ldg(&g_sedge[j + 3]);
        float e0a = __ldg(&g_asrc[s0.x * NHEAD + h]) + adst_h;
        float e1a = __ldg(&g_asrc[s1.x * NHEAD + h]) + adst_h;
        float e2a = __ldg(&g_asrc[s2.x * NHEAD + h]) + adst_h;
        float e3a = __ldg(&g_asrc[s3.x * NHEAD + h]) + adst_h;
        uint2 p0 = __ldg((const uint2*)&g_xhh[(size_t)s0.x * HC + cb]);
        uint2 p1 = __ldg((const uint2*)&g_xhh[(size_t)s1.x * HC + cb]);
        uint2 p2 = __ldg((const uint2*)&g_xhh[(size_t)s2.x * HC + cb]);
        uint2 p3 = __ldg((const uint2*)&g_xhh[(size_t)s3.x * HC + cb]);
        e0a = (e0a > 0.f) ? e0a : 0.2f * e0a;
        e1a = (e1a > 0.f) ? e1a : 0.2f * e1a;
        e2a = (e2a > 0.f) ? e2a : 0.2f * e2a;
        e3a = (e3a > 0.f) ? e3a : 0.2f * e3a;
        float w0 = __expf(e0a), w1 = __expf(e1a);
        float w2 = __expf(e2a), w3 = __expf(e3a);
        dn += (w0 + w1) + (w2 + w3);
        fma4(a0, a1, a2, a3, p0, w0);
        fma4(a0, a1, a2, a3, p1, w1);
        fma4(a0, a1, a2, a3, p2, w2);
        fma4(a0, a1, a2, a3, p3, w3);
    }
    for (; j < end; j++) {
        int2 sa = __ldg(&g_sedge[j]);
        float ea = __ldg(&g_asrc[sa.x * NHEAD + h]) + adst_h;
        ea = (ea > 0.f) ? ea : 0.2f * ea;
        float wa = __expf(ea);
        dn += wa;
        uint2 pa = __ldg((const uint2*)&g_xhh[(size_t)sa.x * HC + cb]);
        fma4(a0, a1, a2, a3, pa, wa);
    }

    float inv = 1.f / (dn + 1e-16f);
    float4 xb = __ldg((const float4*)&x[(size_t)d * HC + cb]);
    float4 bb = __ldg((const float4*)&bias[cb]);
    float4 o  = make_float4(a0 * inv + xb.x + bb.x, a1 * inv + xb.y + bb.y,
                            a2 * inv + xb.z + bb.z, a3 * inv + xb.w + bb.w);
    *(float4*)&out[(size_t)d * HC + cb] = o;

    // ---- alpha pass: this warp covers its 4 heads; 8 edges in flight ----
    if (alpha_out) {
        int hh = hf * 4 + (lane & 3);
        float dnh = __shfl_sync(0xFFFFFFFFu, dn, (lane & 3) * 8) + 1e-16f;
        float adst8 = __ldg(&g_adst[d * NHEAD + hh]);
        if (lane < 4) {
            float es = __ldg(&g_asrc[d * NHEAD + hh]) + adst8;
            es = (es > 0.f) ? es : 0.2f * es;
            alpha_out[(size_t)(E + d) * NHEAD + hh] = __expf(es) / dnh;
        }
        for (int jj = beg + (lane >> 2); jj < end; jj += 8) {
            int2 se = __ldg(&g_sedge[jj]);
            float e = __ldg(&g_asrc[se.x * NHEAD + hh]) + adst8;
            e = (e > 0.f) ? e : 0.2f * e;
            alpha_out[(size_t)se.y * NHEAD + hh] = __expf(e) / dnh;
        }
    }
}

// ---------------- host launcher ---------------------------------------------
extern "C" void kernel_launch(void* const* d_in, const int* in_sizes, int n_in,
                              void* d_out, int out_size) {
    const float* x       = (const float*)d_in[0];
    const void*  ei      = d_in[1];
    const float* W       = (const float*)d_in[2];
    const float* att_src = (const float*)d_in[3];
    const float* att_dst = (const float*)d_in[4];
    const float* bias    = (const float*)d_in[5];

    int Nn   = in_sizes[0] / INC;
    int E    = in_sizes[1] / 2;
    int Etot = E + Nn;

    float* out = (float*)d_out;
    float* alpha_out = nullptr;
    if ((long long)out_size >= (long long)Nn * HC + (long long)Etot * NHEAD)
        alpha_out = out + (size_t)Nn * HC;

    // one-time host objects (no device memory involved)
    static cudaStream_t s1 = nullptr;
    static cudaEvent_t  evFork = nullptr, evJoin = nullptr;
    static int          inited = 0;
    if (!inited) {
        cudaStreamCreateWithFlags(&s1, cudaStreamNonBlocking);
        cudaEventCreateWithFlags(&evFork, cudaEventDisableTiming);
        cudaEventCreateWithFlags(&evJoin, cudaEventDisableTiming);
        cudaFuncSetAttribute(k_gemm, cudaFuncAttributeMaxDynamicSharedMemorySize,
                             SMEM_ELEMS * 2);
        inited = 1;
    }

    // fork: branch stream s1 runs GEMM + logits, main stream builds CSR
    cudaEventRecord(evFork, 0);
    cudaStreamWaitEvent(s1, evFork, 0);

    // --- branch A (s1): projection GEMM + per-node logits ---
    k_gemm<<<(Nn + GBM - 1) / GBM, 512, SMEM_ELEMS * 2, s1>>>(x, W, Nn);
    k_logits<<<(Nn * 32 + 255) / 256, 256, 0, s1>>>(att_src, att_dst, Nn);

    // --- branch B (main stream): edge conversion + CSR build ---
    k_detect<<<1, 256>>>((const int*)ei, 16384);
    k_zero<<<(Nn + 255) / 256, 256>>>(Nn);
    k_convert<<<(2 * E + 255) / 256, 256>>>(ei, 2 * E, E);
    k_scan<<<1, 1024>>>(Nn);
    k_scatter<<<(E + 255) / 256, 256>>>(E);

    // join: main stream waits for branch A
    cudaEventRecord(evJoin, s1);
    cudaStreamWaitEvent(0, evJoin, 0);

    // fused softmax + aggregation + residual + bias + alpha (no atomics)
    k_agg<<<(Nn * 64 + 255) / 256, 256>>>(x, bias, out, alpha_out, Nn, E);
}